// round 2
// baseline (speedup 1.0000x reference)
#include <cuda_runtime.h>
#include <math.h>

#define Bsz 2
#define Sseq 2048
#define Dmodel 2048
#define Hheads 16
#define HDdim 128

// scratch (no cudaMalloc allowed)
__device__ float g_Q[Bsz * Sseq * Dmodel];
__device__ float g_K[Bsz * Sseq * Dmodel];
__device__ float g_V[Bsz * Sseq * Dmodel];
__device__ float g_Y[Bsz * Sseq * Dmodel];

// ---------------------------------------------------------------------------
// GEMM: C[M,N] = A[M,K] * B[N,K]^T   (both operands K-contiguous, like x @ W.T)
// 128x128 block, 256 threads, 8x8 per thread, BK=8, register prefetch.
// ---------------------------------------------------------------------------
#define GBM 128
#define GBN 128
#define GBK 8

__global__ __launch_bounds__(256) void gemm_nt(const float* __restrict__ A,
                                               const float* __restrict__ B,
                                               float* __restrict__ C,
                                               int M, int N, int K)
{
    __shared__ float As[GBK][GBM + 4];
    __shared__ float Bs[GBK][GBN + 4];

    const int tid = threadIdx.x;
    const int tx = tid & 15;        // 0..15 -> col group
    const int ty = tid >> 4;        // 0..15 -> row group
    const int rowBase = blockIdx.y * GBM;
    const int colBase = blockIdx.x * GBN;

    // load mapping: each thread loads one float4 of A and one of B per k-tile
    const int lr = tid >> 1;              // 0..127
    const int lc = (tid & 1) * 4;         // 0 or 4

    const float* Aptr = A + (size_t)(rowBase + lr) * K + lc;
    const float* Bptr = B + (size_t)(colBase + lr) * K + lc;

    float4 a4 = *(const float4*)Aptr;
    float4 b4 = *(const float4*)Bptr;

    float acc[8][8];
#pragma unroll
    for (int i = 0; i < 8; i++)
#pragma unroll
        for (int j = 0; j < 8; j++) acc[i][j] = 0.f;

    const int nt = K / GBK;
    for (int kt = 0; kt < nt; kt++) {
        As[lc + 0][lr] = a4.x; As[lc + 1][lr] = a4.y;
        As[lc + 2][lr] = a4.z; As[lc + 3][lr] = a4.w;
        Bs[lc + 0][lr] = b4.x; Bs[lc + 1][lr] = b4.y;
        Bs[lc + 2][lr] = b4.z; Bs[lc + 3][lr] = b4.w;
        __syncthreads();

        if (kt + 1 < nt) {
            a4 = *(const float4*)(Aptr + (size_t)(kt + 1) * GBK);
            b4 = *(const float4*)(Bptr + (size_t)(kt + 1) * GBK);
        }

#pragma unroll
        for (int kk = 0; kk < GBK; kk++) {
            float ra[8], rb[8];
            *(float4*)&ra[0] = *(const float4*)&As[kk][ty * 8];
            *(float4*)&ra[4] = *(const float4*)&As[kk][ty * 8 + 4];
            *(float4*)&rb[0] = *(const float4*)&Bs[kk][tx * 8];
            *(float4*)&rb[4] = *(const float4*)&Bs[kk][tx * 8 + 4];
#pragma unroll
            for (int i = 0; i < 8; i++)
#pragma unroll
                for (int j = 0; j < 8; j++)
                    acc[i][j] += ra[i] * rb[j];
        }
        __syncthreads();
    }

#pragma unroll
    for (int i = 0; i < 8; i++) {
        const int r = rowBase + ty * 8 + i;
        float4* crow = (float4*)&C[(size_t)r * N + colBase + tx * 8];
        crow[0] = make_float4(acc[i][0], acc[i][1], acc[i][2], acc[i][3]);
        crow[1] = make_float4(acc[i][4], acc[i][5], acc[i][6], acc[i][7]);
    }
}

// ---------------------------------------------------------------------------
// Flash-style causal attention. One CTA = (b, h, 64-query tile).
// Q/K/V layout: (b, s, D) with head slice at column h*128.
// Output Y written in (b, s, D) layout (heads concatenated) ready for Wo GEMM.
// ---------------------------------------------------------------------------
#define ABM 64
#define ABN 64
#define QPAD (HDdim + 1)
#define PPAD (ABN + 1)

// smem floats: 3*64*129 (Q,K,V) + 64*65 (P) + 3*64 (m,l,alpha)
#define ATTN_SMEM_FLOATS (3 * 64 * QPAD + 64 * PPAD + 192)
#define ATTN_SMEM_BYTES (ATTN_SMEM_FLOATS * 4)

__global__ __launch_bounds__(256) void attn_kernel(const float* __restrict__ Q,
                                                   const float* __restrict__ K,
                                                   const float* __restrict__ V,
                                                   float* __restrict__ Y)
{
    extern __shared__ float sm[];
    float (*Qs)[QPAD] = (float(*)[QPAD])sm;
    float (*Ks)[QPAD] = (float(*)[QPAD])(sm + 64 * QPAD);
    float (*Vs)[QPAD] = (float(*)[QPAD])(sm + 2 * 64 * QPAD);
    float (*Ps)[PPAD] = (float(*)[PPAD])(sm + 3 * 64 * QPAD);
    float* m_sh = sm + 3 * 64 * QPAD + 64 * PPAD;
    float* l_sh = m_sh + 64;
    float* al_sh = l_sh + 64;

    const int tid = threadIdx.x;
    const int tx = tid & 15;
    const int ty = tid >> 4;
    const int qt = blockIdx.x;
    const int h = blockIdx.y;
    const int b = blockIdx.z;

    const float scale = 0.08838834764831845f;  // 1/sqrt(128)

    const size_t base = ((size_t)b * Sseq) * Dmodel + (size_t)h * HDdim;

    // load Q tile (64 x 128)
#pragma unroll
    for (int it = 0; it < 8; it++) {
        int idx = it * 256 + tid;     // float4 index, 2048 total
        int r = idx >> 5;             // 32 float4 per row
        int c = (idx & 31) << 2;
        float4 v = *(const float4*)&Q[base + (size_t)(qt * ABM + r) * Dmodel + c];
        Qs[r][c] = v.x; Qs[r][c + 1] = v.y; Qs[r][c + 2] = v.z; Qs[r][c + 3] = v.w;
    }
    if (tid < 64) { m_sh[tid] = -INFINITY; l_sh[tid] = 0.f; }

    float O[4][8];
#pragma unroll
    for (int i = 0; i < 4; i++)
#pragma unroll
        for (int j = 0; j < 8; j++) O[i][j] = 0.f;

    for (int kt = 0; kt <= qt; kt++) {
        __syncthreads();   // protect Ks/Vs from previous iteration's readers
        // load K, V tiles
#pragma unroll
        for (int it = 0; it < 8; it++) {
            int idx = it * 256 + tid;
            int r = idx >> 5;
            int c = (idx & 31) << 2;
            float4 kv = *(const float4*)&K[base + (size_t)(kt * ABN + r) * Dmodel + c];
            Ks[r][c] = kv.x; Ks[r][c + 1] = kv.y; Ks[r][c + 2] = kv.z; Ks[r][c + 3] = kv.w;
            float4 vv = *(const float4*)&V[base + (size_t)(kt * ABN + r) * Dmodel + c];
            Vs[r][c] = vv.x; Vs[r][c + 1] = vv.y; Vs[r][c + 2] = vv.z; Vs[r][c + 3] = vv.w;
        }
        __syncthreads();

        // Phase A: S = Q K^T (rows 4ty+i, cols 4tx+j)
        float s[4][4];
#pragma unroll
        for (int i = 0; i < 4; i++)
#pragma unroll
            for (int j = 0; j < 4; j++) s[i][j] = 0.f;

#pragma unroll 8
        for (int kk = 0; kk < HDdim; kk++) {
            float qa[4], kb[4];
#pragma unroll
            for (int i = 0; i < 4; i++) qa[i] = Qs[4 * ty + i][kk];
#pragma unroll
            for (int j = 0; j < 4; j++) kb[j] = Ks[4 * tx + j][kk];
#pragma unroll
            for (int i = 0; i < 4; i++)
#pragma unroll
                for (int j = 0; j < 4; j++)
                    s[i][j] += qa[i] * kb[j];
        }
        const int q0 = qt * ABM + 4 * ty;
        const int k0 = kt * ABN + 4 * tx;
#pragma unroll
        for (int i = 0; i < 4; i++)
#pragma unroll
            for (int j = 0; j < 4; j++) {
                float val = (k0 + j > q0 + i) ? -INFINITY : s[i][j] * scale;
                Ps[4 * ty + i][4 * tx + j] = val;
            }
        __syncthreads();

        // Phase B: per-row online softmax update (64 rows, 1 thread each)
        if (tid < 64) {
            float mold = m_sh[tid];
            float mx = mold;
            for (int j = 0; j < ABN; j++) mx = fmaxf(mx, Ps[tid][j]);
            float a = (mold == -INFINITY) ? 0.f : __expf(mold - mx);
            float ls = 0.f;
            for (int j = 0; j < ABN; j++) {
                float pv = Ps[tid][j];
                float e = (pv == -INFINITY) ? 0.f : __expf(pv - mx);
                Ps[tid][j] = e;
                ls += e;
            }
            m_sh[tid] = mx;
            l_sh[tid] = l_sh[tid] * a + ls;
            al_sh[tid] = a;
        }
        __syncthreads();

        // Phase C: rescale O, accumulate P @ V (rows 4ty+i, cols tx + 16j)
        float ar[4];
#pragma unroll
        for (int i = 0; i < 4; i++) ar[i] = al_sh[4 * ty + i];
#pragma unroll
        for (int i = 0; i < 4; i++)
#pragma unroll
            for (int j = 0; j < 8; j++) O[i][j] *= ar[i];

#pragma unroll 4
        for (int kk = 0; kk < ABN; kk++) {
            float p[4], vv[8];
#pragma unroll
            for (int i = 0; i < 4; i++) p[i] = Ps[4 * ty + i][kk];
#pragma unroll
            for (int j = 0; j < 8; j++) vv[j] = Vs[kk][tx + 16 * j];
#pragma unroll
            for (int i = 0; i < 4; i++)
#pragma unroll
                for (int j = 0; j < 8; j++)
                    O[i][j] += p[i] * vv[j];
        }
    }

    float linv[4];
#pragma unroll
    for (int i = 0; i < 4; i++) linv[i] = 1.f / l_sh[4 * ty + i];
#pragma unroll
    for (int i = 0; i < 4; i++) {
        size_t row = base + (size_t)(qt * ABM + 4 * ty + i) * Dmodel;
#pragma unroll
        for (int j = 0; j < 8; j++)
            Y[row + tx + 16 * j] = O[i][j] * linv[i];
    }
}

// ---------------------------------------------------------------------------
// launch
// ---------------------------------------------------------------------------
extern "C" void kernel_launch(void* const* d_in, const int* in_sizes, int n_in,
                              void* d_out, int out_size)
{
    (void)in_sizes; (void)n_in; (void)out_size;
    const float* x  = (const float*)d_in[0];
    // d_in[1] = mask (structurally causal triu(k=1); implemented analytically)
    const float* Wq = (const float*)d_in[2];
    const float* Wk = (const float*)d_in[3];
    const float* Wv = (const float*)d_in[4];
    const float* Wo = (const float*)d_in[5];
    float* out = (float*)d_out;

    float *qp, *kp, *vp, *yp;
    cudaGetSymbolAddress((void**)&qp, g_Q);
    cudaGetSymbolAddress((void**)&kp, g_K);
    cudaGetSymbolAddress((void**)&vp, g_V);
    cudaGetSymbolAddress((void**)&yp, g_Y);

    const int M = Bsz * Sseq;           // 4096
    dim3 ggrid(Dmodel / GBN, M / GBM);  // (16, 32)

    gemm_nt<<<ggrid, 256>>>(x, Wq, qp, M, Dmodel, Dmodel);
    gemm_nt<<<ggrid, 256>>>(x, Wk, kp, M, Dmodel, Dmodel);
    gemm_nt<<<ggrid, 256>>>(x, Wv, vp, M, Dmodel, Dmodel);

    cudaFuncSetAttribute(attn_kernel, cudaFuncAttributeMaxDynamicSharedMemorySize,
                         ATTN_SMEM_BYTES);
    attn_kernel<<<dim3(Sseq / ABM, Hheads, Bsz), 256, ATTN_SMEM_BYTES>>>(qp, kp, vp, yp);

    gemm_nt<<<ggrid, 256>>>(yp, Wo, out, M, Dmodel, Dmodel);
}

// round 4
// speedup vs baseline: 1.6494x; 1.6494x over previous
#include <cuda_runtime.h>
#include <cuda_bf16.h>
#include <math.h>
#include <stdint.h>

#define Bsz 2
#define Sseq 2048
#define Dmodel 2048
#define Hheads 16
#define HDdim 128
#define Mrows (Bsz * Sseq)   // 4096

// ---------------- scratch (no cudaMalloc allowed) ----------------
__device__ float g_Q[Mrows * Dmodel];
__device__ float g_K[Mrows * Dmodel];
__device__ float g_V[Mrows * Dmodel];
__device__ float g_Y[Mrows * Dmodel];

// bf16 hi/lo split buffers (raw ushort)
__device__ unsigned short g_xhi[Mrows * Dmodel];
__device__ unsigned short g_xlo[Mrows * Dmodel];
__device__ unsigned short g_yhi[Mrows * Dmodel];
__device__ unsigned short g_ylo[Mrows * Dmodel];
__device__ unsigned short g_wqhi[Dmodel * Dmodel];
__device__ unsigned short g_wqlo[Dmodel * Dmodel];
__device__ unsigned short g_wkhi[Dmodel * Dmodel];
__device__ unsigned short g_wklo[Dmodel * Dmodel];
__device__ unsigned short g_wvhi[Dmodel * Dmodel];
__device__ unsigned short g_wvlo[Dmodel * Dmodel];
__device__ unsigned short g_wohi[Dmodel * Dmodel];
__device__ unsigned short g_wolo[Dmodel * Dmodel];

// ---------------- helpers ----------------
__device__ __forceinline__ uint32_t smem_to_u32(const void* p) {
    uint32_t a;
    asm("{ .reg .u64 t; cvta.to.shared.u64 t, %1; cvt.u32.u64 %0, t; }" : "=r"(a) : "l"(p));
    return a;
}

#define CP_ASYNC16(dst_u32, src_ptr) \
    asm volatile("cp.async.cg.shared.global [%0], [%1], 16;" :: "r"(dst_u32), "l"(src_ptr))
#define CP_COMMIT() asm volatile("cp.async.commit_group;")
#define CP_WAIT1()  asm volatile("cp.async.wait_group 1;")
#define CP_WAIT0()  asm volatile("cp.async.wait_group 0;")

#define LDSM_X4(r0, r1, r2, r3, addr) \
    asm volatile("ldmatrix.sync.aligned.m8n8.x4.shared.b16 {%0,%1,%2,%3}, [%4];" \
                 : "=r"(r0), "=r"(r1), "=r"(r2), "=r"(r3) : "r"(addr))

#define MMA_BF16(c, a, b) \
    asm volatile("mma.sync.aligned.m16n8k16.row.col.f32.bf16.bf16.f32 " \
                 "{%0,%1,%2,%3},{%4,%5,%6,%7},{%8,%9},{%0,%1,%2,%3};" \
                 : "+f"((c)[0]), "+f"((c)[1]), "+f"((c)[2]), "+f"((c)[3]) \
                 : "r"((a)[0]), "r"((a)[1]), "r"((a)[2]), "r"((a)[3]), \
                   "r"((b)[0]), "r"((b)[1]))

// ---------------------------------------------------------------------------
// split: fp32 -> (bf16 hi, bf16 lo)
// ---------------------------------------------------------------------------
__global__ __launch_bounds__(256) void split_kernel(const float* __restrict__ in,
                                                    unsigned short* __restrict__ hi,
                                                    unsigned short* __restrict__ lo,
                                                    int n4)
{
    int i = blockIdx.x * blockDim.x + threadIdx.x;
    if (i >= n4) return;
    float4 v = ((const float4*)in)[i];
    float xs[4] = {v.x, v.y, v.z, v.w};
    unsigned short hs[4], ls[4];
#pragma unroll
    for (int c = 0; c < 4; c++) {
        __nv_bfloat16 bh = __float2bfloat16_rn(xs[c]);
        float r = xs[c] - __bfloat162float(bh);
        __nv_bfloat16 bl = __float2bfloat16_rn(r);
        hs[c] = __bfloat16_as_ushort(bh);
        ls[c] = __bfloat16_as_ushort(bl);
    }
    ushort4 h = {hs[0], hs[1], hs[2], hs[3]};
    ushort4 l = {ls[0], ls[1], ls[2], ls[3]};
    ((ushort4*)hi)[i] = h;
    ((ushort4*)lo)[i] = l;
}

// ---------------------------------------------------------------------------
// mma.sync bf16-split GEMM: C[M,N] = A[M,K] * B[N,K]^T (fp32 via hi/lo split)
// 128x128 CTA, 8 warps (warp tile 32x64), K-chunks of 64, cp.async double buffer.
// smem tile: 128 rows x 64 bf16, row stride 72 elems (144B) -> conflict-free ldmatrix.
// ---------------------------------------------------------------------------
#define GROW 72
#define TILE_B (128 * GROW * 2)     // 18432
#define STAGE_B (4 * TILE_B)        // 73728 : Ahi, Alo, Bhi, Blo
#define GEMM_SMEM_BYTES (2 * STAGE_B)  // 147456

__device__ __forceinline__ void gemm_issue_chunk(
    uint32_t sbase, int buf, int tid,
    const unsigned short* __restrict__ Ahi, const unsigned short* __restrict__ Alo,
    const unsigned short* __restrict__ Bhi, const unsigned short* __restrict__ Blo,
    int rowBase, int colBase, int K, int ch)
{
    const size_t kOff = (size_t)ch * 64;
    const unsigned short* srcs[4] = {
        Ahi + (size_t)rowBase * K + kOff,
        Alo + (size_t)rowBase * K + kOff,
        Bhi + (size_t)colBase * K + kOff,
        Blo + (size_t)colBase * K + kOff };
    const uint32_t stage = sbase + buf * STAGE_B;
#pragma unroll
    for (int t = 0; t < 4; t++) {
        const unsigned short* src = srcs[t];
        const uint32_t dstT = stage + t * TILE_B;
#pragma unroll
        for (int it = 0; it < 4; it++) {
            int idx = it * 256 + tid;   // 0..1023
            int r = idx >> 3;           // row 0..127
            int j = idx & 7;            // 16B chunk
            uint32_t dst = dstT + r * (GROW * 2) + j * 16;
            CP_ASYNC16(dst, src + (size_t)r * K + j * 8);
        }
    }
    CP_COMMIT();
}

__global__ __launch_bounds__(256) void gemm_mma(const unsigned short* __restrict__ Ahi,
                                                const unsigned short* __restrict__ Alo,
                                                const unsigned short* __restrict__ Bhi,
                                                const unsigned short* __restrict__ Blo,
                                                float* __restrict__ C,
                                                int M, int N, int K)
{
    extern __shared__ char smem[];
    const uint32_t sbase = smem_to_u32(smem);
    const int tid = threadIdx.x;
    const int wid = tid >> 5;
    const int lane = tid & 31;

    const int rowBase = blockIdx.y * 128;
    const int colBase = blockIdx.x * 128;
    const int m0 = (wid & 3) * 32;      // warp row offset in tile
    const int n0 = (wid >> 2) * 64;     // warp col offset in tile

    // ldmatrix lane addressing: row-in-16 and k-offset (0 or 8)
    const int lr = (lane & 7) + (lane & 8);
    const int lk = (lane >> 4) << 3;

    float acc[2][8][4];
#pragma unroll
    for (int mt = 0; mt < 2; mt++)
#pragma unroll
        for (int nt = 0; nt < 8; nt++)
#pragma unroll
            for (int q = 0; q < 4; q++) acc[mt][nt][q] = 0.f;

    const int nch = K / 64;
    gemm_issue_chunk(sbase, 0, tid, Ahi, Alo, Bhi, Blo, rowBase, colBase, K, 0);
    gemm_issue_chunk(sbase, 1, tid, Ahi, Alo, Bhi, Blo, rowBase, colBase, K, 1);

    for (int ch = 0; ch < nch; ch++) {
        if (ch == nch - 1) { CP_WAIT0(); } else { CP_WAIT1(); }
        __syncthreads();

        const int buf = ch & 1;
        const uint32_t aHiB = sbase + buf * STAGE_B;
        const uint32_t aLoB = aHiB + TILE_B;
        const uint32_t bHiB = aHiB + 2 * TILE_B;
        const uint32_t bLoB = aHiB + 3 * TILE_B;

#pragma unroll
        for (int ks = 0; ks < 4; ks++) {
            const int k0 = ks * 16;
            uint32_t ahi[2][4], alo[2][4];
#pragma unroll
            for (int mt = 0; mt < 2; mt++) {
                uint32_t off = (m0 + mt * 16 + lr) * (GROW * 2) + (k0 + lk) * 2;
                LDSM_X4(ahi[mt][0], ahi[mt][1], ahi[mt][2], ahi[mt][3], aHiB + off);
                LDSM_X4(alo[mt][0], alo[mt][1], alo[mt][2], alo[mt][3], aLoB + off);
            }
            uint32_t bhi[8][2], blo[8][2];
#pragma unroll
            for (int j = 0; j < 4; j++) {
                uint32_t off = (n0 + j * 16 + lr) * (GROW * 2) + (k0 + lk) * 2;
                uint32_t r0, r1, r2, r3;
                LDSM_X4(r0, r1, r2, r3, bHiB + off);
                bhi[2 * j][0] = r0; bhi[2 * j][1] = r2;
                bhi[2 * j + 1][0] = r1; bhi[2 * j + 1][1] = r3;
                LDSM_X4(r0, r1, r2, r3, bLoB + off);
                blo[2 * j][0] = r0; blo[2 * j][1] = r2;
                blo[2 * j + 1][0] = r1; blo[2 * j + 1][1] = r3;
            }
#pragma unroll
            for (int mt = 0; mt < 2; mt++)
#pragma unroll
                for (int nt = 0; nt < 8; nt++) {
                    MMA_BF16(acc[mt][nt], ahi[mt], bhi[nt]);
                    MMA_BF16(acc[mt][nt], ahi[mt], blo[nt]);
                    MMA_BF16(acc[mt][nt], alo[mt], bhi[nt]);
                }
        }
        __syncthreads();
        if (ch + 2 < nch)
            gemm_issue_chunk(sbase, buf, tid, Ahi, Alo, Bhi, Blo, rowBase, colBase, K, ch + 2);
    }

    // epilogue
    const int cr = lane >> 2;
    const int cc = (lane & 3) * 2;
#pragma unroll
    for (int mt = 0; mt < 2; mt++) {
#pragma unroll
        for (int nt = 0; nt < 8; nt++) {
            const int row = rowBase + m0 + mt * 16 + cr;
            const int col = colBase + n0 + nt * 8 + cc;
            *(float2*)&C[(size_t)row * N + col] = make_float2(acc[mt][nt][0], acc[mt][nt][1]);
            *(float2*)&C[(size_t)(row + 8) * N + col] = make_float2(acc[mt][nt][2], acc[mt][nt][3]);
        }
    }
}

// ---------------------------------------------------------------------------
// Flash-style causal attention (unchanged from passing baseline).
// ---------------------------------------------------------------------------
#define ABM 64
#define ABN 64
#define QPAD (HDdim + 1)
#define PPAD (ABN + 1)
#define ATTN_SMEM_FLOATS (3 * 64 * QPAD + 64 * PPAD + 192)
#define ATTN_SMEM_BYTES (ATTN_SMEM_FLOATS * 4)

__global__ __launch_bounds__(256) void attn_kernel(const float* __restrict__ Q,
                                                   const float* __restrict__ K,
                                                   const float* __restrict__ V,
                                                   float* __restrict__ Y)
{
    extern __shared__ float sm[];
    float (*Qs)[QPAD] = (float(*)[QPAD])sm;
    float (*Ks)[QPAD] = (float(*)[QPAD])(sm + 64 * QPAD);
    float (*Vs)[QPAD] = (float(*)[QPAD])(sm + 2 * 64 * QPAD);
    float (*Ps)[PPAD] = (float(*)[PPAD])(sm + 3 * 64 * QPAD);
    float* m_sh = sm + 3 * 64 * QPAD + 64 * PPAD;
    float* l_sh = m_sh + 64;
    float* al_sh = l_sh + 64;

    const int tid = threadIdx.x;
    const int tx = tid & 15;
    const int ty = tid >> 4;
    const int qt = blockIdx.x;
    const int h = blockIdx.y;
    const int b = blockIdx.z;
    const float scale = 0.08838834764831845f;
    const size_t base = ((size_t)b * Sseq) * Dmodel + (size_t)h * HDdim;

#pragma unroll
    for (int it = 0; it < 8; it++) {
        int idx = it * 256 + tid;
        int r = idx >> 5;
        int c = (idx & 31) << 2;
        float4 v = *(const float4*)&Q[base + (size_t)(qt * ABM + r) * Dmodel + c];
        Qs[r][c] = v.x; Qs[r][c + 1] = v.y; Qs[r][c + 2] = v.z; Qs[r][c + 3] = v.w;
    }
    if (tid < 64) { m_sh[tid] = -INFINITY; l_sh[tid] = 0.f; }

    float O[4][8];
#pragma unroll
    for (int i = 0; i < 4; i++)
#pragma unroll
        for (int j = 0; j < 8; j++) O[i][j] = 0.f;

    for (int kt = 0; kt <= qt; kt++) {
        __syncthreads();
#pragma unroll
        for (int it = 0; it < 8; it++) {
            int idx = it * 256 + tid;
            int r = idx >> 5;
            int c = (idx & 31) << 2;
            float4 kv = *(const float4*)&K[base + (size_t)(kt * ABN + r) * Dmodel + c];
            Ks[r][c] = kv.x; Ks[r][c + 1] = kv.y; Ks[r][c + 2] = kv.z; Ks[r][c + 3] = kv.w;
            float4 vv = *(const float4*)&V[base + (size_t)(kt * ABN + r) * Dmodel + c];
            Vs[r][c] = vv.x; Vs[r][c + 1] = vv.y; Vs[r][c + 2] = vv.z; Vs[r][c + 3] = vv.w;
        }
        __syncthreads();

        float s[4][4];
#pragma unroll
        for (int i = 0; i < 4; i++)
#pragma unroll
            for (int j = 0; j < 4; j++) s[i][j] = 0.f;
#pragma unroll 8
        for (int kk = 0; kk < HDdim; kk++) {
            float qa[4], kb[4];
#pragma unroll
            for (int i = 0; i < 4; i++) qa[i] = Qs[4 * ty + i][kk];
#pragma unroll
            for (int j = 0; j < 4; j++) kb[j] = Ks[4 * tx + j][kk];
#pragma unroll
            for (int i = 0; i < 4; i++)
#pragma unroll
                for (int j = 0; j < 4; j++)
                    s[i][j] += qa[i] * kb[j];
        }
        const int q0 = qt * ABM + 4 * ty;
        const int k0 = kt * ABN + 4 * tx;
#pragma unroll
        for (int i = 0; i < 4; i++)
#pragma unroll
            for (int j = 0; j < 4; j++) {
                float val = (k0 + j > q0 + i) ? -INFINITY : s[i][j] * scale;
                Ps[4 * ty + i][4 * tx + j] = val;
            }
        __syncthreads();

        if (tid < 64) {
            float mold = m_sh[tid];
            float mx = mold;
            for (int j = 0; j < ABN; j++) mx = fmaxf(mx, Ps[tid][j]);
            float a = (mold == -INFINITY) ? 0.f : __expf(mold - mx);
            float ls = 0.f;
            for (int j = 0; j < ABN; j++) {
                float pv = Ps[tid][j];
                float e = (pv == -INFINITY) ? 0.f : __expf(pv - mx);
                Ps[tid][j] = e;
                ls += e;
            }
            m_sh[tid] = mx;
            l_sh[tid] = l_sh[tid] * a + ls;
            al_sh[tid] = a;
        }
        __syncthreads();

        float ar[4];
#pragma unroll
        for (int i = 0; i < 4; i++) ar[i] = al_sh[4 * ty + i];
#pragma unroll
        for (int i = 0; i < 4; i++)
#pragma unroll
            for (int j = 0; j < 8; j++) O[i][j] *= ar[i];

#pragma unroll 4
        for (int kk = 0; kk < ABN; kk++) {
            float p[4], vv[8];
#pragma unroll
            for (int i = 0; i < 4; i++) p[i] = Ps[4 * ty + i][kk];
#pragma unroll
            for (int j = 0; j < 8; j++) vv[j] = Vs[kk][tx + 16 * j];
#pragma unroll
            for (int i = 0; i < 4; i++)
#pragma unroll
                for (int j = 0; j < 8; j++)
                    O[i][j] += p[i] * vv[j];
        }
    }

    float linv[4];
#pragma unroll
    for (int i = 0; i < 4; i++) linv[i] = 1.f / l_sh[4 * ty + i];
#pragma unroll
    for (int i = 0; i < 4; i++) {
        size_t row = base + (size_t)(qt * ABM + 4 * ty + i) * Dmodel;
#pragma unroll
        for (int j = 0; j < 8; j++)
            Y[row + tx + 16 * j] = O[i][j] * linv[i];
    }
}

// ---------------------------------------------------------------------------
// launch
// ---------------------------------------------------------------------------
extern "C" void kernel_launch(void* const* d_in, const int* in_sizes, int n_in,
                              void* d_out, int out_size)
{
    (void)in_sizes; (void)n_in; (void)out_size;
    const float* x  = (const float*)d_in[0];
    const float* Wq = (const float*)d_in[2];
    const float* Wk = (const float*)d_in[3];
    const float* Wv = (const float*)d_in[4];
    const float* Wo = (const float*)d_in[5];
    float* out = (float*)d_out;

    float *qp, *kp, *vp, *yp;
    cudaGetSymbolAddress((void**)&qp, g_Q);
    cudaGetSymbolAddress((void**)&kp, g_K);
    cudaGetSymbolAddress((void**)&vp, g_V);
    cudaGetSymbolAddress((void**)&yp, g_Y);

    unsigned short *xhi, *xlo, *yhi, *ylo;
    unsigned short *wqhi, *wqlo, *wkhi, *wklo, *wvhi, *wvlo, *wohi, *wolo;
    cudaGetSymbolAddress((void**)&xhi, g_xhi);   cudaGetSymbolAddress((void**)&xlo, g_xlo);
    cudaGetSymbolAddress((void**)&yhi, g_yhi);   cudaGetSymbolAddress((void**)&ylo, g_ylo);
    cudaGetSymbolAddress((void**)&wqhi, g_wqhi); cudaGetSymbolAddress((void**)&wqlo, g_wqlo);
    cudaGetSymbolAddress((void**)&wkhi, g_wkhi); cudaGetSymbolAddress((void**)&wklo, g_wklo);
    cudaGetSymbolAddress((void**)&wvhi, g_wvhi); cudaGetSymbolAddress((void**)&wvlo, g_wvlo);
    cudaGetSymbolAddress((void**)&wohi, g_wohi); cudaGetSymbolAddress((void**)&wolo, g_wolo);

    cudaFuncSetAttribute(gemm_mma, cudaFuncAttributeMaxDynamicSharedMemorySize, GEMM_SMEM_BYTES);
    cudaFuncSetAttribute(attn_kernel, cudaFuncAttributeMaxDynamicSharedMemorySize, ATTN_SMEM_BYTES);

    const int nX4 = Mrows * Dmodel / 4;
    const int nW4 = Dmodel * Dmodel / 4;

    split_kernel<<<nX4 / 256, 256>>>(x, xhi, xlo, nX4);
    split_kernel<<<nW4 / 256, 256>>>(Wq, wqhi, wqlo, nW4);
    split_kernel<<<nW4 / 256, 256>>>(Wk, wkhi, wklo, nW4);
    split_kernel<<<nW4 / 256, 256>>>(Wv, wvhi, wvlo, nW4);
    split_kernel<<<nW4 / 256, 256>>>(Wo, wohi, wolo, nW4);

    dim3 ggrid(Dmodel / 128, Mrows / 128);   // (16, 32)
    gemm_mma<<<ggrid, 256, GEMM_SMEM_BYTES>>>(xhi, xlo, wqhi, wqlo, qp, Mrows, Dmodel, Dmodel);
    gemm_mma<<<ggrid, 256, GEMM_SMEM_BYTES>>>(xhi, xlo, wkhi, wklo, kp, Mrows, Dmodel, Dmodel);
    gemm_mma<<<ggrid, 256, GEMM_SMEM_BYTES>>>(xhi, xlo, wvhi, wvlo, vp, Mrows, Dmodel, Dmodel);

    attn_kernel<<<dim3(Sseq / ABM, Hheads, Bsz), 256, ATTN_SMEM_BYTES>>>(qp, kp, vp, yp);

    split_kernel<<<nX4 / 256, 256>>>(yp, yhi, ylo, nX4);
    gemm_mma<<<ggrid, 256, GEMM_SMEM_BYTES>>>(yhi, ylo, wohi, wolo, out, Mrows, Dmodel, Dmodel);
}

// round 5
// speedup vs baseline: 2.5349x; 1.5369x over previous
#include <cuda_runtime.h>
#include <cuda_bf16.h>
#include <math.h>
#include <stdint.h>

#define Bsz 2
#define Sseq 2048
#define Dmodel 2048
#define Hheads 16
#define HDdim 128
#define Mrows (Bsz * Sseq)   // 4096

// ---------------- scratch (no cudaMalloc allowed) ----------------
__device__ unsigned short g_xhi[Mrows * Dmodel];
__device__ unsigned short g_xlo[Mrows * Dmodel];
__device__ unsigned short g_qhi[Mrows * Dmodel];
__device__ unsigned short g_qlo[Mrows * Dmodel];
__device__ unsigned short g_khi[Mrows * Dmodel];
__device__ unsigned short g_klo[Mrows * Dmodel];
__device__ unsigned short g_vhi[Mrows * Dmodel];
__device__ unsigned short g_vlo[Mrows * Dmodel];
__device__ unsigned short g_yhi[Mrows * Dmodel];
__device__ unsigned short g_ylo[Mrows * Dmodel];
__device__ unsigned short g_wqhi[Dmodel * Dmodel];
__device__ unsigned short g_wqlo[Dmodel * Dmodel];
__device__ unsigned short g_wkhi[Dmodel * Dmodel];
__device__ unsigned short g_wklo[Dmodel * Dmodel];
__device__ unsigned short g_wvhi[Dmodel * Dmodel];
__device__ unsigned short g_wvlo[Dmodel * Dmodel];
__device__ unsigned short g_wohi[Dmodel * Dmodel];
__device__ unsigned short g_wolo[Dmodel * Dmodel];

// ---------------- helpers ----------------
__device__ __forceinline__ uint32_t smem_to_u32(const void* p) {
    uint32_t a;
    asm("{ .reg .u64 t; cvta.to.shared.u64 t, %1; cvt.u32.u64 %0, t; }" : "=r"(a) : "l"(p));
    return a;
}

#define CP_ASYNC16(dst_u32, src_ptr) \
    asm volatile("cp.async.cg.shared.global [%0], [%1], 16;" :: "r"(dst_u32), "l"(src_ptr))
#define CP_COMMIT() asm volatile("cp.async.commit_group;")
#define CP_WAIT1()  asm volatile("cp.async.wait_group 1;")
#define CP_WAIT0()  asm volatile("cp.async.wait_group 0;")

#define LDSM_X4(r0, r1, r2, r3, addr) \
    asm volatile("ldmatrix.sync.aligned.m8n8.x4.shared.b16 {%0,%1,%2,%3}, [%4];" \
                 : "=r"(r0), "=r"(r1), "=r"(r2), "=r"(r3) : "r"(addr))
#define LDSM_X4_T(r0, r1, r2, r3, addr) \
    asm volatile("ldmatrix.sync.aligned.m8n8.x4.trans.shared.b16 {%0,%1,%2,%3}, [%4];" \
                 : "=r"(r0), "=r"(r1), "=r"(r2), "=r"(r3) : "r"(addr))

#define MMA_BF16(c, a, b) \
    asm volatile("mma.sync.aligned.m16n8k16.row.col.f32.bf16.bf16.f32 " \
                 "{%0,%1,%2,%3},{%4,%5,%6,%7},{%8,%9},{%0,%1,%2,%3};" \
                 : "+f"((c)[0]), "+f"((c)[1]), "+f"((c)[2]), "+f"((c)[3]) \
                 : "r"((a)[0]), "r"((a)[1]), "r"((a)[2]), "r"((a)[3]), \
                   "r"((b)[0]), "r"((b)[1]))

__device__ __forceinline__ float fast_ex2(float x) {
    float y; asm("ex2.approx.f32 %0, %1;" : "=f"(y) : "f"(x)); return y;
}

// pack two fp32 into bf16x2 hi word + bf16x2 residual (lo) word
__device__ __forceinline__ void pack_hilo(float a, float b, uint32_t& h, uint32_t& l) {
    asm("cvt.rn.bf16x2.f32 %0, %1, %2;" : "=r"(h) : "f"(b), "f"(a));  // lo-half=a, hi-half=b
    float fa = __uint_as_float(h << 16);
    float fb = __uint_as_float(h & 0xffff0000u);
    asm("cvt.rn.bf16x2.f32 %0, %1, %2;" : "=r"(l) : "f"(b - fb), "f"(a - fa));
}

// ---------------------------------------------------------------------------
// split: fp32 -> (bf16 hi, bf16 lo)
// ---------------------------------------------------------------------------
__global__ __launch_bounds__(256) void split_kernel(const float* __restrict__ in,
                                                    unsigned short* __restrict__ hi,
                                                    unsigned short* __restrict__ lo,
                                                    int n4)
{
    int i = blockIdx.x * blockDim.x + threadIdx.x;
    if (i >= n4) return;
    float4 v = ((const float4*)in)[i];
    uint32_t h0, l0, h1, l1;
    pack_hilo(v.x, v.y, h0, l0);
    pack_hilo(v.z, v.w, h1, l1);
    ((uint2*)hi)[i] = make_uint2(h0, h1);
    ((uint2*)lo)[i] = make_uint2(l0, l1);
}

// ---------------------------------------------------------------------------
// mma.sync bf16-split GEMM: C[M,N] = A[M,K] * B[N,K]^T
// SPLIT_OUT=1 writes bf16 hi/lo pair instead of fp32.
// ---------------------------------------------------------------------------
#define GROW 72
#define TILE_B (128 * GROW * 2)
#define STAGE_B (4 * TILE_B)
#define GEMM_SMEM_BYTES (2 * STAGE_B)

__device__ __forceinline__ void gemm_issue_chunk(
    uint32_t sbase, int buf, int tid,
    const unsigned short* __restrict__ Ahi, const unsigned short* __restrict__ Alo,
    const unsigned short* __restrict__ Bhi, const unsigned short* __restrict__ Blo,
    int rowBase, int colBase, int K, int ch)
{
    const size_t kOff = (size_t)ch * 64;
    const unsigned short* srcs[4] = {
        Ahi + (size_t)rowBase * K + kOff,
        Alo + (size_t)rowBase * K + kOff,
        Bhi + (size_t)colBase * K + kOff,
        Blo + (size_t)colBase * K + kOff };
    const uint32_t stage = sbase + buf * STAGE_B;
#pragma unroll
    for (int t = 0; t < 4; t++) {
        const unsigned short* src = srcs[t];
        const uint32_t dstT = stage + t * TILE_B;
#pragma unroll
        for (int it = 0; it < 4; it++) {
            int idx = it * 256 + tid;
            int r = idx >> 3;
            int j = idx & 7;
            CP_ASYNC16(dstT + r * (GROW * 2) + j * 16, src + (size_t)r * K + j * 8);
        }
    }
    CP_COMMIT();
}

template<int SPLIT_OUT>
__global__ __launch_bounds__(256) void gemm_mma(const unsigned short* __restrict__ Ahi,
                                                const unsigned short* __restrict__ Alo,
                                                const unsigned short* __restrict__ Bhi,
                                                const unsigned short* __restrict__ Blo,
                                                float* __restrict__ C,
                                                unsigned short* __restrict__ Chi,
                                                unsigned short* __restrict__ Clo,
                                                int M, int N, int K)
{
    extern __shared__ char smem[];
    const uint32_t sbase = smem_to_u32(smem);
    const int tid = threadIdx.x;
    const int wid = tid >> 5;
    const int lane = tid & 31;

    const int rowBase = blockIdx.y * 128;
    const int colBase = blockIdx.x * 128;
    const int m0 = (wid & 3) * 32;
    const int n0 = (wid >> 2) * 64;

    const int lr = (lane & 7) + (lane & 8);
    const int lk = (lane >> 4) << 3;

    float acc[2][8][4];
#pragma unroll
    for (int mt = 0; mt < 2; mt++)
#pragma unroll
        for (int nt = 0; nt < 8; nt++)
#pragma unroll
            for (int q = 0; q < 4; q++) acc[mt][nt][q] = 0.f;

    const int nch = K / 64;
    gemm_issue_chunk(sbase, 0, tid, Ahi, Alo, Bhi, Blo, rowBase, colBase, K, 0);
    gemm_issue_chunk(sbase, 1, tid, Ahi, Alo, Bhi, Blo, rowBase, colBase, K, 1);

    for (int ch = 0; ch < nch; ch++) {
        if (ch == nch - 1) { CP_WAIT0(); } else { CP_WAIT1(); }
        __syncthreads();

        const int buf = ch & 1;
        const uint32_t aHiB = sbase + buf * STAGE_B;
        const uint32_t aLoB = aHiB + TILE_B;
        const uint32_t bHiB = aHiB + 2 * TILE_B;
        const uint32_t bLoB = aHiB + 3 * TILE_B;

#pragma unroll
        for (int ks = 0; ks < 4; ks++) {
            const int k0 = ks * 16;
            uint32_t ahi[2][4], alo[2][4];
#pragma unroll
            for (int mt = 0; mt < 2; mt++) {
                uint32_t off = (m0 + mt * 16 + lr) * (GROW * 2) + (k0 + lk) * 2;
                LDSM_X4(ahi[mt][0], ahi[mt][1], ahi[mt][2], ahi[mt][3], aHiB + off);
                LDSM_X4(alo[mt][0], alo[mt][1], alo[mt][2], alo[mt][3], aLoB + off);
            }
            uint32_t bhi[8][2], blo[8][2];
#pragma unroll
            for (int j = 0; j < 4; j++) {
                uint32_t off = (n0 + j * 16 + lr) * (GROW * 2) + (k0 + lk) * 2;
                uint32_t r0, r1, r2, r3;
                LDSM_X4(r0, r1, r2, r3, bHiB + off);
                bhi[2 * j][0] = r0; bhi[2 * j][1] = r2;
                bhi[2 * j + 1][0] = r1; bhi[2 * j + 1][1] = r3;
                LDSM_X4(r0, r1, r2, r3, bLoB + off);
                blo[2 * j][0] = r0; blo[2 * j][1] = r2;
                blo[2 * j + 1][0] = r1; blo[2 * j + 1][1] = r3;
            }
#pragma unroll
            for (int mt = 0; mt < 2; mt++)
#pragma unroll
                for (int nt = 0; nt < 8; nt++) {
                    MMA_BF16(acc[mt][nt], ahi[mt], bhi[nt]);
                    MMA_BF16(acc[mt][nt], ahi[mt], blo[nt]);
                    MMA_BF16(acc[mt][nt], alo[mt], bhi[nt]);
                }
        }
        __syncthreads();
        if (ch + 2 < nch)
            gemm_issue_chunk(sbase, buf, tid, Ahi, Alo, Bhi, Blo, rowBase, colBase, K, ch + 2);
    }

    const int cr = lane >> 2;
    const int cc = (lane & 3) * 2;
#pragma unroll
    for (int mt = 0; mt < 2; mt++) {
#pragma unroll
        for (int nt = 0; nt < 8; nt++) {
            const int row = rowBase + m0 + mt * 16 + cr;
            const int col = colBase + n0 + nt * 8 + cc;
            if (SPLIT_OUT) {
                uint32_t h, l;
                pack_hilo(acc[mt][nt][0], acc[mt][nt][1], h, l);
                *(uint32_t*)(Chi + (size_t)row * N + col) = h;
                *(uint32_t*)(Clo + (size_t)row * N + col) = l;
                pack_hilo(acc[mt][nt][2], acc[mt][nt][3], h, l);
                *(uint32_t*)(Chi + (size_t)(row + 8) * N + col) = h;
                *(uint32_t*)(Clo + (size_t)(row + 8) * N + col) = l;
            } else {
                *(float2*)&C[(size_t)row * N + col] = make_float2(acc[mt][nt][0], acc[mt][nt][1]);
                *(float2*)&C[(size_t)(row + 8) * N + col] = make_float2(acc[mt][nt][2], acc[mt][nt][3]);
            }
        }
    }
}

// ---------------------------------------------------------------------------
// Flash attention with mma.sync bf16 hi/lo splits.
// CTA = 128-query tile x (h, b). 8 warps, each owns 16 rows.
// K/V 64-key tiles, cp.async double buffered. P stays in registers.
// ---------------------------------------------------------------------------
#define ASTRIDE 272                    // bytes per smem tile row (128 bf16 + pad)
#define ATILE_B (64 * ASTRIDE)         // 17408
#define ASTAGE_B (4 * ATILE_B)         // 69632: Khi, Klo, Vhi, Vlo
#define ATTN_SMEM (2 * ASTAGE_B)       // 139264

__device__ __forceinline__ void attn_issue_kv(
    uint32_t sbase, int buf, int tid,
    const unsigned short* __restrict__ khi, const unsigned short* __restrict__ klo,
    const unsigned short* __restrict__ vhi, const unsigned short* __restrict__ vlo,
    size_t hbase, int kt)
{
    const unsigned short* srcs[4] = {khi, klo, vhi, vlo};
    const uint32_t stage = sbase + buf * ASTAGE_B;
#pragma unroll
    for (int t = 0; t < 4; t++) {
        const unsigned short* src = srcs[t] + hbase + (size_t)(kt * 64) * Dmodel;
        const uint32_t dstT = stage + t * ATILE_B;
#pragma unroll
        for (int it = 0; it < 4; it++) {
            int idx = it * 256 + tid;     // 0..1023
            int r = idx >> 4;             // row 0..63
            int j = idx & 15;             // 16B chunk 0..15
            CP_ASYNC16(dstT + r * ASTRIDE + j * 16, src + (size_t)r * Dmodel + j * 8);
        }
    }
    CP_COMMIT();
}

__global__ __launch_bounds__(256, 1) void attn_mma(
    const unsigned short* __restrict__ qhi, const unsigned short* __restrict__ qlo,
    const unsigned short* __restrict__ khi, const unsigned short* __restrict__ klo,
    const unsigned short* __restrict__ vhi, const unsigned short* __restrict__ vlo,
    unsigned short* __restrict__ yhi, unsigned short* __restrict__ ylo)
{
    extern __shared__ char smem[];
    const uint32_t sbase = smem_to_u32(smem);
    const int tid = threadIdx.x;
    const int wid = tid >> 5;
    const int lane = tid & 31;

    const int qt = (gridDim.x - 1) - blockIdx.x;   // heavy tiles first
    const int h = blockIdx.y;
    const int b = blockIdx.z;
    const size_t hbase = ((size_t)b * Sseq) * Dmodel + (size_t)h * HDdim;

    const int lr = (lane & 7) + (lane & 8);
    const int lk = (lane >> 4) << 3;
    const float kExp = 1.4426950408889634f * 0.08838834764831845f;  // log2e / sqrt(128)

    // ---- stage Q (128 x 128 bf16 hi+lo) through stage0 smem into register frags
    {
#pragma unroll
        for (int it = 0; it < 8; it++) {
            int idx = it * 256 + tid;    // 0..2047
            int r = idx >> 4;
            int j = idx & 15;
            const size_t goff = hbase + (size_t)(qt * 128 + r) * Dmodel + j * 8;
            CP_ASYNC16(sbase + r * ASTRIDE + j * 16, qhi + goff);
            CP_ASYNC16(sbase + 128 * ASTRIDE + r * ASTRIDE + j * 16, qlo + goff);
        }
        CP_COMMIT(); CP_WAIT0();
        __syncthreads();
    }
    uint32_t qfh[8][4], qfl[8][4];
#pragma unroll
    for (int ks = 0; ks < 8; ks++) {
        uint32_t off = (wid * 16 + lr) * ASTRIDE + (ks * 16 + lk) * 2;
        LDSM_X4(qfh[ks][0], qfh[ks][1], qfh[ks][2], qfh[ks][3], sbase + off);
        LDSM_X4(qfl[ks][0], qfl[ks][1], qfl[ks][2], qfl[ks][3], sbase + 128 * ASTRIDE + off);
    }
    __syncthreads();

    float oacc[16][4];
#pragma unroll
    for (int nt = 0; nt < 16; nt++)
#pragma unroll
        for (int q = 0; q < 4; q++) oacc[nt][q] = 0.f;
    float m0 = -1e30f, m1 = -1e30f, l0 = 0.f, l1 = 0.f;

    const int nkt = 2 * qt + 2;
    attn_issue_kv(sbase, 0, tid, khi, klo, vhi, vlo, hbase, 0);
    if (nkt > 1) attn_issue_kv(sbase, 1, tid, khi, klo, vhi, vlo, hbase, 1);

    const int row0 = qt * 128 + wid * 16 + (lane >> 2);

    for (int kt = 0; kt < nkt; kt++) {
        if (kt == nkt - 1) { CP_WAIT0(); } else { CP_WAIT1(); }
        __syncthreads();

        const bool active = (kt * 64) <= (qt * 128 + wid * 16 + 15);
        if (active) {
            const uint32_t stage = sbase + (kt & 1) * ASTAGE_B;
            const uint32_t kHiB = stage;
            const uint32_t kLoB = stage + ATILE_B;
            const uint32_t vHiB = stage + 2 * ATILE_B;
            const uint32_t vLoB = stage + 3 * ATILE_B;

            // ---- S = Q K^T (bf16 3-pass)
            float sacc[8][4];
#pragma unroll
            for (int nt = 0; nt < 8; nt++)
#pragma unroll
                for (int q = 0; q < 4; q++) sacc[nt][q] = 0.f;
#pragma unroll
            for (int ks = 0; ks < 8; ks++) {
#pragma unroll
                for (int jp = 0; jp < 4; jp++) {
                    uint32_t off = (jp * 16 + lr) * ASTRIDE + (ks * 16 + lk) * 2;
                    uint32_t r0, r1, r2, r3, s0, s1, s2, s3;
                    LDSM_X4(r0, r1, r2, r3, kHiB + off);
                    LDSM_X4(s0, s1, s2, s3, kLoB + off);
                    uint32_t bh0[2] = {r0, r2}, bh1[2] = {r1, r3};
                    uint32_t bl0[2] = {s0, s2}, bl1[2] = {s1, s3};
                    MMA_BF16(sacc[2 * jp], qfh[ks], bh0);
                    MMA_BF16(sacc[2 * jp], qfh[ks], bl0);
                    MMA_BF16(sacc[2 * jp], qfl[ks], bh0);
                    MMA_BF16(sacc[2 * jp + 1], qfh[ks], bh1);
                    MMA_BF16(sacc[2 * jp + 1], qfh[ks], bl1);
                    MMA_BF16(sacc[2 * jp + 1], qfl[ks], bh1);
                }
            }

            // ---- online softmax (base-2, scale folded), causal mask
            const bool needm = (kt * 64 + 63) > (qt * 128 + wid * 16);
            const int col0 = kt * 64 + 2 * (lane & 3);
            float mx0 = -1e30f, mx1 = -1e30f;
#pragma unroll
            for (int nt = 0; nt < 8; nt++) {
#pragma unroll
                for (int e = 0; e < 2; e++) {
                    float v = sacc[nt][e] * kExp;
                    if (needm && (col0 + nt * 8 + e > row0)) v = -1e30f;
                    sacc[nt][e] = v;
                    mx0 = fmaxf(mx0, v);
                    float w = sacc[nt][2 + e] * kExp;
                    if (needm && (col0 + nt * 8 + e > row0 + 8)) w = -1e30f;
                    sacc[nt][2 + e] = w;
                    mx1 = fmaxf(mx1, w);
                }
            }
            mx0 = fmaxf(mx0, __shfl_xor_sync(0xffffffffu, mx0, 1));
            mx0 = fmaxf(mx0, __shfl_xor_sync(0xffffffffu, mx0, 2));
            mx1 = fmaxf(mx1, __shfl_xor_sync(0xffffffffu, mx1, 1));
            mx1 = fmaxf(mx1, __shfl_xor_sync(0xffffffffu, mx1, 2));
            float mn0 = fmaxf(m0, mx0), mn1 = fmaxf(m1, mx1);
            float a0 = fast_ex2(m0 - mn0), a1 = fast_ex2(m1 - mn1);
#pragma unroll
            for (int nt = 0; nt < 16; nt++) {
                oacc[nt][0] *= a0; oacc[nt][1] *= a0;
                oacc[nt][2] *= a1; oacc[nt][3] *= a1;
            }
            float ls0 = 0.f, ls1 = 0.f;
#pragma unroll
            for (int nt = 0; nt < 8; nt++) {
#pragma unroll
                for (int e = 0; e < 2; e++) {
                    float p0 = fast_ex2(sacc[nt][e] - mn0);
                    float p1 = fast_ex2(sacc[nt][2 + e] - mn1);
                    sacc[nt][e] = p0; sacc[nt][2 + e] = p1;
                    ls0 += p0; ls1 += p1;
                }
            }
            ls0 += __shfl_xor_sync(0xffffffffu, ls0, 1);
            ls0 += __shfl_xor_sync(0xffffffffu, ls0, 2);
            ls1 += __shfl_xor_sync(0xffffffffu, ls1, 1);
            ls1 += __shfl_xor_sync(0xffffffffu, ls1, 2);
            l0 = l0 * a0 + ls0; l1 = l1 * a1 + ls1;
            m0 = mn0; m1 = mn1;

            // ---- O += P V (bf16 3-pass; P fragments built from S accumulators)
#pragma unroll
            for (int kstep = 0; kstep < 4; kstep++) {
                uint32_t ph[4], pl[4];
                pack_hilo(sacc[2 * kstep][0], sacc[2 * kstep][1], ph[0], pl[0]);
                pack_hilo(sacc[2 * kstep][2], sacc[2 * kstep][3], ph[1], pl[1]);
                pack_hilo(sacc[2 * kstep + 1][0], sacc[2 * kstep + 1][1], ph[2], pl[2]);
                pack_hilo(sacc[2 * kstep + 1][2], sacc[2 * kstep + 1][3], ph[3], pl[3]);
#pragma unroll
                for (int dp = 0; dp < 8; dp++) {
                    uint32_t off = (kstep * 16 + lr) * ASTRIDE + (dp * 16 + lk) * 2;
                    uint32_t v0, v1, v2, v3, w0, w1, w2, w3;
                    LDSM_X4_T(v0, v1, v2, v3, vHiB + off);
                    LDSM_X4_T(w0, w1, w2, w3, vLoB + off);
                    uint32_t bh0[2] = {v0, v1}, bh1[2] = {v2, v3};
                    uint32_t bl0[2] = {w0, w1}, bl1[2] = {w2, w3};
                    MMA_BF16(oacc[2 * dp], ph, bh0);
                    MMA_BF16(oacc[2 * dp], ph, bl0);
                    MMA_BF16(oacc[2 * dp], pl, bh0);
                    MMA_BF16(oacc[2 * dp + 1], ph, bh1);
                    MMA_BF16(oacc[2 * dp + 1], ph, bl1);
                    MMA_BF16(oacc[2 * dp + 1], pl, bh1);
                }
            }
        }
        __syncthreads();
        if (kt + 2 < nkt)
            attn_issue_kv(sbase, kt & 1, tid, khi, klo, vhi, vlo, hbase, kt + 2);
    }

    // ---- epilogue: normalize, split to bf16 hi/lo, store
    const float inv0 = 1.f / l0;
    const float inv1 = 1.f / l1;
#pragma unroll
    for (int nt = 0; nt < 16; nt++) {
        const int col = nt * 8 + 2 * (lane & 3);
        const size_t i0 = ((size_t)b * Sseq + row0) * Dmodel + h * HDdim + col;
        const size_t i1 = ((size_t)b * Sseq + row0 + 8) * Dmodel + h * HDdim + col;
        uint32_t hh, ll;
        pack_hilo(oacc[nt][0] * inv0, oacc[nt][1] * inv0, hh, ll);
        *(uint32_t*)(yhi + i0) = hh;
        *(uint32_t*)(ylo + i0) = ll;
        pack_hilo(oacc[nt][2] * inv1, oacc[nt][3] * inv1, hh, ll);
        *(uint32_t*)(yhi + i1) = hh;
        *(uint32_t*)(ylo + i1) = ll;
    }
}

// ---------------------------------------------------------------------------
// launch
// ---------------------------------------------------------------------------
extern "C" void kernel_launch(void* const* d_in, const int* in_sizes, int n_in,
                              void* d_out, int out_size)
{
    (void)in_sizes; (void)n_in; (void)out_size;
    const float* x  = (const float*)d_in[0];
    const float* Wq = (const float*)d_in[2];
    const float* Wk = (const float*)d_in[3];
    const float* Wv = (const float*)d_in[4];
    const float* Wo = (const float*)d_in[5];
    float* out = (float*)d_out;

    unsigned short *xhi, *xlo, *qhi, *qlo, *khi, *klo, *vhi, *vlo, *yhi, *ylo;
    unsigned short *wqhi, *wqlo, *wkhi, *wklo, *wvhi, *wvlo, *wohi, *wolo;
    cudaGetSymbolAddress((void**)&xhi, g_xhi);   cudaGetSymbolAddress((void**)&xlo, g_xlo);
    cudaGetSymbolAddress((void**)&qhi, g_qhi);   cudaGetSymbolAddress((void**)&qlo, g_qlo);
    cudaGetSymbolAddress((void**)&khi, g_khi);   cudaGetSymbolAddress((void**)&klo, g_klo);
    cudaGetSymbolAddress((void**)&vhi, g_vhi);   cudaGetSymbolAddress((void**)&vlo, g_vlo);
    cudaGetSymbolAddress((void**)&yhi, g_yhi);   cudaGetSymbolAddress((void**)&ylo, g_ylo);
    cudaGetSymbolAddress((void**)&wqhi, g_wqhi); cudaGetSymbolAddress((void**)&wqlo, g_wqlo);
    cudaGetSymbolAddress((void**)&wkhi, g_wkhi); cudaGetSymbolAddress((void**)&wklo, g_wklo);
    cudaGetSymbolAddress((void**)&wvhi, g_wvhi); cudaGetSymbolAddress((void**)&wvlo, g_wvlo);
    cudaGetSymbolAddress((void**)&wohi, g_wohi); cudaGetSymbolAddress((void**)&wolo, g_wolo);

    cudaFuncSetAttribute(gemm_mma<0>, cudaFuncAttributeMaxDynamicSharedMemorySize, GEMM_SMEM_BYTES);
    cudaFuncSetAttribute(gemm_mma<1>, cudaFuncAttributeMaxDynamicSharedMemorySize, GEMM_SMEM_BYTES);
    cudaFuncSetAttribute(attn_mma, cudaFuncAttributeMaxDynamicSharedMemorySize, ATTN_SMEM);

    const int nX4 = Mrows * Dmodel / 4;
    const int nW4 = Dmodel * Dmodel / 4;

    split_kernel<<<nX4 / 256, 256>>>(x, xhi, xlo, nX4);
    split_kernel<<<nW4 / 256, 256>>>(Wq, wqhi, wqlo, nW4);
    split_kernel<<<nW4 / 256, 256>>>(Wk, wkhi, wklo, nW4);
    split_kernel<<<nW4 / 256, 256>>>(Wv, wvhi, wvlo, nW4);
    split_kernel<<<nW4 / 256, 256>>>(Wo, wohi, wolo, nW4);

    dim3 ggrid(Dmodel / 128, Mrows / 128);   // (16, 32)
    gemm_mma<1><<<ggrid, 256, GEMM_SMEM_BYTES>>>(xhi, xlo, wqhi, wqlo, nullptr, qhi, qlo, Mrows, Dmodel, Dmodel);
    gemm_mma<1><<<ggrid, 256, GEMM_SMEM_BYTES>>>(xhi, xlo, wkhi, wklo, nullptr, khi, klo, Mrows, Dmodel, Dmodel);
    gemm_mma<1><<<ggrid, 256, GEMM_SMEM_BYTES>>>(xhi, xlo, wvhi, wvlo, nullptr, vhi, vlo, Mrows, Dmodel, Dmodel);

    attn_mma<<<dim3(Sseq / 128, Hheads, Bsz), 256, ATTN_SMEM>>>(qhi, qlo, khi, klo, vhi, vlo, yhi, ylo);

    gemm_mma<0><<<ggrid, 256, GEMM_SMEM_BYTES>>>(yhi, ylo, wohi, wolo, out, nullptr, nullptr, Mrows, Dmodel, Dmodel);
}

// round 6
// speedup vs baseline: 2.7341x; 1.0786x over previous
#include <cuda_runtime.h>
#include <cuda_bf16.h>
#include <math.h>
#include <stdint.h>

#define Bsz 2
#define Sseq 2048
#define Dmodel 2048
#define Hheads 16
#define HDdim 128
#define Mrows (Bsz * Sseq)   // 4096

// ---------------- scratch (no cudaMalloc allowed) ----------------
__device__ unsigned short g_xhi[Mrows * Dmodel];
__device__ unsigned short g_xlo[Mrows * Dmodel];
__device__ unsigned short g_qhi[Mrows * Dmodel];
__device__ unsigned short g_qlo[Mrows * Dmodel];
__device__ unsigned short g_khi[Mrows * Dmodel];
__device__ unsigned short g_klo[Mrows * Dmodel];
__device__ unsigned short g_vhi[Mrows * Dmodel];
__device__ unsigned short g_vlo[Mrows * Dmodel];
__device__ unsigned short g_yhi[Mrows * Dmodel];
__device__ unsigned short g_ylo[Mrows * Dmodel];
__device__ unsigned short g_wqhi[Dmodel * Dmodel];
__device__ unsigned short g_wqlo[Dmodel * Dmodel];
__device__ unsigned short g_wkhi[Dmodel * Dmodel];
__device__ unsigned short g_wklo[Dmodel * Dmodel];
__device__ unsigned short g_wvhi[Dmodel * Dmodel];
__device__ unsigned short g_wvlo[Dmodel * Dmodel];
__device__ unsigned short g_wohi[Dmodel * Dmodel];
__device__ unsigned short g_wolo[Dmodel * Dmodel];

// ---------------- helpers ----------------
__device__ __forceinline__ uint32_t smem_to_u32(const void* p) {
    uint32_t a;
    asm("{ .reg .u64 t; cvta.to.shared.u64 t, %1; cvt.u32.u64 %0, t; }" : "=r"(a) : "l"(p));
    return a;
}

#define CP_ASYNC16(dst_u32, src_ptr) \
    asm volatile("cp.async.cg.shared.global [%0], [%1], 16;" :: "r"(dst_u32), "l"(src_ptr))
#define CP_COMMIT() asm volatile("cp.async.commit_group;")
#define CP_WAIT1()  asm volatile("cp.async.wait_group 1;")
#define CP_WAIT0()  asm volatile("cp.async.wait_group 0;")

#define LDSM_X4(r0, r1, r2, r3, addr) \
    asm volatile("ldmatrix.sync.aligned.m8n8.x4.shared.b16 {%0,%1,%2,%3}, [%4];" \
                 : "=r"(r0), "=r"(r1), "=r"(r2), "=r"(r3) : "r"(addr))
#define LDSM_X4_T(r0, r1, r2, r3, addr) \
    asm volatile("ldmatrix.sync.aligned.m8n8.x4.trans.shared.b16 {%0,%1,%2,%3}, [%4];" \
                 : "=r"(r0), "=r"(r1), "=r"(r2), "=r"(r3) : "r"(addr))

#define MMA_BF16(c, a, b) \
    asm volatile("mma.sync.aligned.m16n8k16.row.col.f32.bf16.bf16.f32 " \
                 "{%0,%1,%2,%3},{%4,%5,%6,%7},{%8,%9},{%0,%1,%2,%3};" \
                 : "+f"((c)[0]), "+f"((c)[1]), "+f"((c)[2]), "+f"((c)[3]) \
                 : "r"((a)[0]), "r"((a)[1]), "r"((a)[2]), "r"((a)[3]), \
                   "r"((b)[0]), "r"((b)[1]))

__device__ __forceinline__ float fast_ex2(float x) {
    float y; asm("ex2.approx.f32 %0, %1;" : "=f"(y) : "f"(x)); return y;
}

__device__ __forceinline__ void pack_hilo(float a, float b, uint32_t& h, uint32_t& l) {
    asm("cvt.rn.bf16x2.f32 %0, %1, %2;" : "=r"(h) : "f"(b), "f"(a));
    float fa = __uint_as_float(h << 16);
    float fb = __uint_as_float(h & 0xffff0000u);
    asm("cvt.rn.bf16x2.f32 %0, %1, %2;" : "=r"(l) : "f"(b - fb), "f"(a - fa));
}

// ---------------------------------------------------------------------------
// splits
// ---------------------------------------------------------------------------
__device__ __forceinline__ void split_one(const float* in, unsigned short* hi,
                                          unsigned short* lo, int i) {
    float4 v = ((const float4*)in)[i];
    uint32_t h0, l0, h1, l1;
    pack_hilo(v.x, v.y, h0, l0);
    pack_hilo(v.z, v.w, h1, l1);
    ((uint2*)hi)[i] = make_uint2(h0, h1);
    ((uint2*)lo)[i] = make_uint2(l0, l1);
}

__global__ __launch_bounds__(256) void split_x(const float* __restrict__ x) {
    int i = blockIdx.x * blockDim.x + threadIdx.x;
    split_one(x, g_xhi, g_xlo, i);
}

__global__ __launch_bounds__(256) void split_w(const float* __restrict__ Wq,
                                               const float* __restrict__ Wk,
                                               const float* __restrict__ Wv,
                                               const float* __restrict__ Wo) {
    int i = blockIdx.x * blockDim.x + threadIdx.x;
    int z = blockIdx.z;
    const float* src = (z == 0) ? Wq : (z == 1) ? Wk : (z == 2) ? Wv : Wo;
    unsigned short* hi = (z == 0) ? g_wqhi : (z == 1) ? g_wkhi : (z == 2) ? g_wvhi : g_wohi;
    unsigned short* lo = (z == 0) ? g_wqlo : (z == 1) ? g_wklo : (z == 2) ? g_wvlo : g_wolo;
    split_one(src, hi, lo, i);
}

// ---------------------------------------------------------------------------
// GEMM core: C[256x128 tile] = A[M,K] * B[N,K]^T, bf16 hi/lo 3-pass.
// 512 threads, 16 warps (8 row-groups x 2 col-groups), warp tile 32x64.
// K-chunks of 64, cp.async double buffer. smem row stride 144B (64 bf16 + pad).
// ---------------------------------------------------------------------------
#define GROWB 144                      // bytes per smem row
#define AT_B (256 * GROWB)             // 36864
#define BT_B (128 * GROWB)             // 18432
#define G2_STAGE (2 * AT_B + 2 * BT_B) // 110592
#define G2_SMEM (2 * G2_STAGE)         // 221184

__device__ __forceinline__ void gemm_issue2(
    uint32_t sbase, int buf, int tid,
    const unsigned short* __restrict__ Ahi, const unsigned short* __restrict__ Alo,
    const unsigned short* __restrict__ Bhi, const unsigned short* __restrict__ Blo,
    int rowBase, int colBase, int ch)
{
    const size_t kOff = (size_t)ch * 64;
    const uint32_t stage = sbase + buf * G2_STAGE;
    const unsigned short* a0 = Ahi + (size_t)rowBase * Dmodel + kOff;
    const unsigned short* a1 = Alo + (size_t)rowBase * Dmodel + kOff;
    const unsigned short* b0 = Bhi + (size_t)colBase * Dmodel + kOff;
    const unsigned short* b1 = Blo + (size_t)colBase * Dmodel + kOff;
#pragma unroll
    for (int it = 0; it < 4; it++) {
        int idx = it * 512 + tid; int r = idx >> 3, j = idx & 7;
        CP_ASYNC16(stage + r * GROWB + j * 16, a0 + (size_t)r * Dmodel + j * 8);
    }
#pragma unroll
    for (int it = 0; it < 4; it++) {
        int idx = it * 512 + tid; int r = idx >> 3, j = idx & 7;
        CP_ASYNC16(stage + AT_B + r * GROWB + j * 16, a1 + (size_t)r * Dmodel + j * 8);
    }
#pragma unroll
    for (int it = 0; it < 2; it++) {
        int idx = it * 512 + tid; int r = idx >> 3, j = idx & 7;
        CP_ASYNC16(stage + 2 * AT_B + r * GROWB + j * 16, b0 + (size_t)r * Dmodel + j * 8);
    }
#pragma unroll
    for (int it = 0; it < 2; it++) {
        int idx = it * 512 + tid; int r = idx >> 3, j = idx & 7;
        CP_ASYNC16(stage + 2 * AT_B + BT_B + r * GROWB + j * 16, b1 + (size_t)r * Dmodel + j * 8);
    }
    CP_COMMIT();
}

template<int SPLIT_OUT>
__device__ __forceinline__ void gemm_core(
    const unsigned short* __restrict__ Ahi, const unsigned short* __restrict__ Alo,
    const unsigned short* __restrict__ Bhi, const unsigned short* __restrict__ Blo,
    float* __restrict__ C, unsigned short* __restrict__ Chi, unsigned short* __restrict__ Clo)
{
    extern __shared__ char smem[];
    const uint32_t sbase = smem_to_u32(smem);
    const int tid = threadIdx.x;
    const int wid = tid >> 5;
    const int lane = tid & 31;

    const int rowBase = blockIdx.y * 256;
    const int colBase = blockIdx.x * 128;
    const int m0 = (wid & 7) * 32;
    const int n0 = (wid >> 3) * 64;

    const int lr = (lane & 7) + (lane & 8);
    const int lk = (lane >> 4) << 3;

    float acc[2][8][4];
#pragma unroll
    for (int mt = 0; mt < 2; mt++)
#pragma unroll
        for (int nt = 0; nt < 8; nt++)
#pragma unroll
            for (int q = 0; q < 4; q++) acc[mt][nt][q] = 0.f;

    const int nch = Dmodel / 64;   // 32
    gemm_issue2(sbase, 0, tid, Ahi, Alo, Bhi, Blo, rowBase, colBase, 0);
    gemm_issue2(sbase, 1, tid, Ahi, Alo, Bhi, Blo, rowBase, colBase, 1);

    for (int ch = 0; ch < nch; ch++) {
        if (ch == nch - 1) { CP_WAIT0(); } else { CP_WAIT1(); }
        __syncthreads();

        const int buf = ch & 1;
        const uint32_t aHiB = sbase + buf * G2_STAGE;
        const uint32_t aLoB = aHiB + AT_B;
        const uint32_t bHiB = aHiB + 2 * AT_B;
        const uint32_t bLoB = bHiB + BT_B;

#pragma unroll
        for (int ks = 0; ks < 4; ks++) {
            const int k0 = ks * 16;
            uint32_t ahi[2][4], alo[2][4];
#pragma unroll
            for (int mt = 0; mt < 2; mt++) {
                uint32_t off = (m0 + mt * 16 + lr) * GROWB + (k0 + lk) * 2;
                LDSM_X4(ahi[mt][0], ahi[mt][1], ahi[mt][2], ahi[mt][3], aHiB + off);
                LDSM_X4(alo[mt][0], alo[mt][1], alo[mt][2], alo[mt][3], aLoB + off);
            }
            uint32_t bf[8][2];
#pragma unroll
            for (int jp = 0; jp < 4; jp++) {
                uint32_t off = (n0 + jp * 16 + lr) * GROWB + (k0 + lk) * 2;
                uint32_t r0, r1, r2, r3;
                LDSM_X4(r0, r1, r2, r3, bHiB + off);
                bf[2 * jp][0] = r0; bf[2 * jp][1] = r2;
                bf[2 * jp + 1][0] = r1; bf[2 * jp + 1][1] = r3;
            }
            // pass 1: Ahi * Bhi (16 independent MMAs)
#pragma unroll
            for (int mt = 0; mt < 2; mt++)
#pragma unroll
                for (int nt = 0; nt < 8; nt++) MMA_BF16(acc[mt][nt], ahi[mt], bf[nt]);
            // pass 2: Alo * Bhi
#pragma unroll
            for (int mt = 0; mt < 2; mt++)
#pragma unroll
                for (int nt = 0; nt < 8; nt++) MMA_BF16(acc[mt][nt], alo[mt], bf[nt]);
            // reload B-lo fragments, pass 3: Ahi * Blo
#pragma unroll
            for (int jp = 0; jp < 4; jp++) {
                uint32_t off = (n0 + jp * 16 + lr) * GROWB + (k0 + lk) * 2;
                uint32_t r0, r1, r2, r3;
                LDSM_X4(r0, r1, r2, r3, bLoB + off);
                bf[2 * jp][0] = r0; bf[2 * jp][1] = r2;
                bf[2 * jp + 1][0] = r1; bf[2 * jp + 1][1] = r3;
            }
#pragma unroll
            for (int mt = 0; mt < 2; mt++)
#pragma unroll
                for (int nt = 0; nt < 8; nt++) MMA_BF16(acc[mt][nt], ahi[mt], bf[nt]);
        }
        __syncthreads();
        if (ch + 2 < nch)
            gemm_issue2(sbase, buf, tid, Ahi, Alo, Bhi, Blo, rowBase, colBase, ch + 2);
    }

    const int cr = lane >> 2;
    const int cc = (lane & 3) * 2;
#pragma unroll
    for (int mt = 0; mt < 2; mt++) {
#pragma unroll
        for (int nt = 0; nt < 8; nt++) {
            const int row = rowBase + m0 + mt * 16 + cr;
            const int col = colBase + n0 + nt * 8 + cc;
            if (SPLIT_OUT) {
                uint32_t h, l;
                pack_hilo(acc[mt][nt][0], acc[mt][nt][1], h, l);
                *(uint32_t*)(Chi + (size_t)row * Dmodel + col) = h;
                *(uint32_t*)(Clo + (size_t)row * Dmodel + col) = l;
                pack_hilo(acc[mt][nt][2], acc[mt][nt][3], h, l);
                *(uint32_t*)(Chi + (size_t)(row + 8) * Dmodel + col) = h;
                *(uint32_t*)(Clo + (size_t)(row + 8) * Dmodel + col) = l;
            } else {
                *(float2*)&C[(size_t)row * Dmodel + col] = make_float2(acc[mt][nt][0], acc[mt][nt][1]);
                *(float2*)&C[(size_t)(row + 8) * Dmodel + col] = make_float2(acc[mt][nt][2], acc[mt][nt][3]);
            }
        }
    }
}

__global__ __launch_bounds__(512) void gemm_qkv() {
    const int z = blockIdx.z;
    const unsigned short* bh = (z == 0) ? g_wqhi : (z == 1) ? g_wkhi : g_wvhi;
    const unsigned short* bl = (z == 0) ? g_wqlo : (z == 1) ? g_wklo : g_wvlo;
    unsigned short* ch = (z == 0) ? g_qhi : (z == 1) ? g_khi : g_vhi;
    unsigned short* cl = (z == 0) ? g_qlo : (z == 1) ? g_klo : g_vlo;
    gemm_core<1>(g_xhi, g_xlo, bh, bl, nullptr, ch, cl);
}

__global__ __launch_bounds__(512) void gemm_wo(float* __restrict__ out) {
    gemm_core<0>(g_yhi, g_ylo, g_wohi, g_wolo, out, nullptr, nullptr);
}

// ---------------------------------------------------------------------------
// Flash attention, mma.sync bf16 hi/lo splits (pass-interleaved MMA ordering).
// ---------------------------------------------------------------------------
#define ASTRIDE 272
#define ATILE_B (64 * ASTRIDE)
#define ASTAGE_B (4 * ATILE_B)
#define ATTN_SMEM (2 * ASTAGE_B)

__device__ __forceinline__ void attn_issue_kv(uint32_t sbase, int buf, int tid,
                                              size_t hbase, int kt)
{
    const unsigned short* srcs[4] = {g_khi, g_klo, g_vhi, g_vlo};
    const uint32_t stage = sbase + buf * ASTAGE_B;
#pragma unroll
    for (int t = 0; t < 4; t++) {
        const unsigned short* src = srcs[t] + hbase + (size_t)(kt * 64) * Dmodel;
        const uint32_t dstT = stage + t * ATILE_B;
#pragma unroll
        for (int it = 0; it < 4; it++) {
            int idx = it * 256 + tid;
            int r = idx >> 4;
            int j = idx & 15;
            CP_ASYNC16(dstT + r * ASTRIDE + j * 16, src + (size_t)r * Dmodel + j * 8);
        }
    }
    CP_COMMIT();
}

__global__ __launch_bounds__(256, 1) void attn_mma()
{
    extern __shared__ char smem[];
    const uint32_t sbase = smem_to_u32(smem);
    const int tid = threadIdx.x;
    const int wid = tid >> 5;
    const int lane = tid & 31;

    const int qt = (gridDim.x - 1) - blockIdx.x;
    const int h = blockIdx.y;
    const int b = blockIdx.z;
    const size_t hbase = ((size_t)b * Sseq) * Dmodel + (size_t)h * HDdim;

    const int lr = (lane & 7) + (lane & 8);
    const int lk = (lane >> 4) << 3;
    const float kExp = 1.4426950408889634f * 0.08838834764831845f;

    {
#pragma unroll
        for (int it = 0; it < 8; it++) {
            int idx = it * 256 + tid;
            int r = idx >> 4;
            int j = idx & 15;
            const size_t goff = hbase + (size_t)(qt * 128 + r) * Dmodel + j * 8;
            CP_ASYNC16(sbase + r * ASTRIDE + j * 16, g_qhi + goff);
            CP_ASYNC16(sbase + 128 * ASTRIDE + r * ASTRIDE + j * 16, g_qlo + goff);
        }
        CP_COMMIT(); CP_WAIT0();
        __syncthreads();
    }
    uint32_t qfh[8][4], qfl[8][4];
#pragma unroll
    for (int ks = 0; ks < 8; ks++) {
        uint32_t off = (wid * 16 + lr) * ASTRIDE + (ks * 16 + lk) * 2;
        LDSM_X4(qfh[ks][0], qfh[ks][1], qfh[ks][2], qfh[ks][3], sbase + off);
        LDSM_X4(qfl[ks][0], qfl[ks][1], qfl[ks][2], qfl[ks][3], sbase + 128 * ASTRIDE + off);
    }
    __syncthreads();

    float oacc[16][4];
#pragma unroll
    for (int nt = 0; nt < 16; nt++)
#pragma unroll
        for (int q = 0; q < 4; q++) oacc[nt][q] = 0.f;
    float m0 = -1e30f, m1 = -1e30f, l0 = 0.f, l1 = 0.f;

    const int nkt = 2 * qt + 2;
    attn_issue_kv(sbase, 0, tid, hbase, 0);
    if (nkt > 1) attn_issue_kv(sbase, 1, tid, hbase, 1);

    const int row0 = qt * 128 + wid * 16 + (lane >> 2);

    for (int kt = 0; kt < nkt; kt++) {
        if (kt == nkt - 1) { CP_WAIT0(); } else { CP_WAIT1(); }
        __syncthreads();

        const bool active = (kt * 64) <= (qt * 128 + wid * 16 + 15);
        if (active) {
            const uint32_t stage = sbase + (kt & 1) * ASTAGE_B;
            const uint32_t kHiB = stage;
            const uint32_t kLoB = stage + ATILE_B;
            const uint32_t vHiB = stage + 2 * ATILE_B;
            const uint32_t vLoB = stage + 3 * ATILE_B;

            float sacc[8][4];
#pragma unroll
            for (int nt = 0; nt < 8; nt++)
#pragma unroll
                for (int q = 0; q < 4; q++) sacc[nt][q] = 0.f;
#pragma unroll
            for (int ks = 0; ks < 8; ks++) {
#pragma unroll
                for (int jp = 0; jp < 4; jp++) {
                    uint32_t off = (jp * 16 + lr) * ASTRIDE + (ks * 16 + lk) * 2;
                    uint32_t r0, r1, r2, r3, s0, s1, s2, s3;
                    LDSM_X4(r0, r1, r2, r3, kHiB + off);
                    LDSM_X4(s0, s1, s2, s3, kLoB + off);
                    uint32_t bh0[2] = {r0, r2}, bh1[2] = {r1, r3};
                    uint32_t bl0[2] = {s0, s2}, bl1[2] = {s1, s3};
                    MMA_BF16(sacc[2 * jp], qfh[ks], bh0);
                    MMA_BF16(sacc[2 * jp + 1], qfh[ks], bh1);
                    MMA_BF16(sacc[2 * jp], qfl[ks], bh0);
                    MMA_BF16(sacc[2 * jp + 1], qfl[ks], bh1);
                    MMA_BF16(sacc[2 * jp], qfh[ks], bl0);
                    MMA_BF16(sacc[2 * jp + 1], qfh[ks], bl1);
                }
            }

            const bool needm = (kt * 64 + 63) > (qt * 128 + wid * 16);
            const int col0 = kt * 64 + 2 * (lane & 3);
            float mx0 = -1e30f, mx1 = -1e30f;
#pragma unroll
            for (int nt = 0; nt < 8; nt++) {
#pragma unroll
                for (int e = 0; e < 2; e++) {
                    float v = sacc[nt][e] * kExp;
                    if (needm && (col0 + nt * 8 + e > row0)) v = -1e30f;
                    sacc[nt][e] = v;
                    mx0 = fmaxf(mx0, v);
                    float w = sacc[nt][2 + e] * kExp;
                    if (needm && (col0 + nt * 8 + e > row0 + 8)) w = -1e30f;
                    sacc[nt][2 + e] = w;
                    mx1 = fmaxf(mx1, w);
                }
            }
            mx0 = fmaxf(mx0, __shfl_xor_sync(0xffffffffu, mx0, 1));
            mx0 = fmaxf(mx0, __shfl_xor_sync(0xffffffffu, mx0, 2));
            mx1 = fmaxf(mx1, __shfl_xor_sync(0xffffffffu, mx1, 1));
            mx1 = fmaxf(mx1, __shfl_xor_sync(0xffffffffu, mx1, 2));
            float mn0 = fmaxf(m0, mx0), mn1 = fmaxf(m1, mx1);
            float a0 = fast_ex2(m0 - mn0), a1 = fast_ex2(m1 - mn1);
#pragma unroll
            for (int nt = 0; nt < 16; nt++) {
                oacc[nt][0] *= a0; oacc[nt][1] *= a0;
                oacc[nt][2] *= a1; oacc[nt][3] *= a1;
            }
            float ls0 = 0.f, ls1 = 0.f;
#pragma unroll
            for (int nt = 0; nt < 8; nt++) {
#pragma unroll
                for (int e = 0; e < 2; e++) {
                    float p0 = fast_ex2(sacc[nt][e] - mn0);
                    float p1 = fast_ex2(sacc[nt][2 + e] - mn1);
                    sacc[nt][e] = p0; sacc[nt][2 + e] = p1;
                    ls0 += p0; ls1 += p1;
                }
            }
            ls0 += __shfl_xor_sync(0xffffffffu, ls0, 1);
            ls0 += __shfl_xor_sync(0xffffffffu, ls0, 2);
            ls1 += __shfl_xor_sync(0xffffffffu, ls1, 1);
            ls1 += __shfl_xor_sync(0xffffffffu, ls1, 2);
            l0 = l0 * a0 + ls0; l1 = l1 * a1 + ls1;
            m0 = mn0; m1 = mn1;

#pragma unroll
            for (int kstep = 0; kstep < 4; kstep++) {
                uint32_t ph[4], pl[4];
                pack_hilo(sacc[2 * kstep][0], sacc[2 * kstep][1], ph[0], pl[0]);
                pack_hilo(sacc[2 * kstep][2], sacc[2 * kstep][3], ph[1], pl[1]);
                pack_hilo(sacc[2 * kstep + 1][0], sacc[2 * kstep + 1][1], ph[2], pl[2]);
                pack_hilo(sacc[2 * kstep + 1][2], sacc[2 * kstep + 1][3], ph[3], pl[3]);
#pragma unroll
                for (int dp = 0; dp < 8; dp++) {
                    uint32_t off = (kstep * 16 + lr) * ASTRIDE + (dp * 16 + lk) * 2;
                    uint32_t v0, v1, v2, v3, w0, w1, w2, w3;
                    LDSM_X4_T(v0, v1, v2, v3, vHiB + off);
                    LDSM_X4_T(w0, w1, w2, w3, vLoB + off);
                    uint32_t bh0[2] = {v0, v1}, bh1[2] = {v2, v3};
                    uint32_t bl0[2] = {w0, w1}, bl1[2] = {w2, w3};
                    MMA_BF16(oacc[2 * dp], ph, bh0);
                    MMA_BF16(oacc[2 * dp + 1], ph, bh1);
                    MMA_BF16(oacc[2 * dp], pl, bh0);
                    MMA_BF16(oacc[2 * dp + 1], pl, bh1);
                    MMA_BF16(oacc[2 * dp], ph, bl0);
                    MMA_BF16(oacc[2 * dp + 1], ph, bl1);
                }
            }
        }
        __syncthreads();
        if (kt + 2 < nkt)
            attn_issue_kv(sbase, kt & 1, tid, hbase, kt + 2);
    }

    const float inv0 = 1.f / l0;
    const float inv1 = 1.f / l1;
#pragma unroll
    for (int nt = 0; nt < 16; nt++) {
        const int col = nt * 8 + 2 * (lane & 3);
        const size_t i0 = ((size_t)b * Sseq + row0) * Dmodel + h * HDdim + col;
        const size_t i1 = ((size_t)b * Sseq + row0 + 8) * Dmodel + h * HDdim + col;
        uint32_t hh, ll;
        pack_hilo(oacc[nt][0] * inv0, oacc[nt][1] * inv0, hh, ll);
        *(uint32_t*)(g_yhi + i0) = hh;
        *(uint32_t*)(g_ylo + i0) = ll;
        pack_hilo(oacc[nt][2] * inv1, oacc[nt][3] * inv1, hh, ll);
        *(uint32_t*)(g_yhi + i1) = hh;
        *(uint32_t*)(g_ylo + i1) = ll;
    }
}

// ---------------------------------------------------------------------------
// launch
// ---------------------------------------------------------------------------
extern "C" void kernel_launch(void* const* d_in, const int* in_sizes, int n_in,
                              void* d_out, int out_size)
{
    (void)in_sizes; (void)n_in; (void)out_size;
    const float* x  = (const float*)d_in[0];
    const float* Wq = (const float*)d_in[2];
    const float* Wk = (const float*)d_in[3];
    const float* Wv = (const float*)d_in[4];
    const float* Wo = (const float*)d_in[5];
    float* out = (float*)d_out;

    cudaFuncSetAttribute(gemm_qkv, cudaFuncAttributeMaxDynamicSharedMemorySize, G2_SMEM);
    cudaFuncSetAttribute(gemm_wo, cudaFuncAttributeMaxDynamicSharedMemorySize, G2_SMEM);
    cudaFuncSetAttribute(attn_mma, cudaFuncAttributeMaxDynamicSharedMemorySize, ATTN_SMEM);

    const int nX4 = Mrows * Dmodel / 4;
    const int nW4 = Dmodel * Dmodel / 4;

    split_x<<<nX4 / 256, 256>>>(x);
    split_w<<<dim3(nW4 / 256, 1, 4), 256>>>(Wq, Wk, Wv, Wo);

    gemm_qkv<<<dim3(Dmodel / 128, Mrows / 256, 3), 512, G2_SMEM>>>();
    attn_mma<<<dim3(Sseq / 128, Hheads, Bsz), 256, ATTN_SMEM>>>();
    gemm_wo<<<dim3(Dmodel / 128, Mrows / 256, 1), 512, G2_SMEM>>>(out);
}

// round 7
// speedup vs baseline: 3.8185x; 1.3967x over previous
#include <cuda_runtime.h>
#include <cuda_fp16.h>
#include <math.h>
#include <stdint.h>

#define Bsz 2
#define Sseq 2048
#define Dmodel 2048
#define Hheads 16
#define HDdim 128
#define Mrows (Bsz * Sseq)   // 4096

// ---------------- scratch (fp16 payloads in ushort arrays) ----------------
__device__ unsigned short g_xhi[Mrows * Dmodel];
__device__ unsigned short g_xlo[Mrows * Dmodel];
__device__ unsigned short g_qhi[Mrows * Dmodel];
__device__ unsigned short g_qlo[Mrows * Dmodel];
__device__ unsigned short g_khi[Mrows * Dmodel];
__device__ unsigned short g_vhi[Mrows * Dmodel];
__device__ unsigned short g_yhi[Mrows * Dmodel];
__device__ unsigned short g_ylo[Mrows * Dmodel];
__device__ unsigned short g_wq[Dmodel * Dmodel];
__device__ unsigned short g_wk[Dmodel * Dmodel];
__device__ unsigned short g_wv[Dmodel * Dmodel];
__device__ unsigned short g_wo[Dmodel * Dmodel];

// ---------------- helpers ----------------
__device__ __forceinline__ uint32_t smem_to_u32(const void* p) {
    uint32_t a;
    asm("{ .reg .u64 t; cvta.to.shared.u64 t, %1; cvt.u32.u64 %0, t; }" : "=r"(a) : "l"(p));
    return a;
}

#define CP_ASYNC16(dst_u32, src_ptr) \
    asm volatile("cp.async.cg.shared.global [%0], [%1], 16;" :: "r"(dst_u32), "l"(src_ptr))
#define CP_COMMIT() asm volatile("cp.async.commit_group;")
#define CP_WAIT1()  asm volatile("cp.async.wait_group 1;")
#define CP_WAIT0()  asm volatile("cp.async.wait_group 0;")

#define LDSM_X4(r0, r1, r2, r3, addr) \
    asm volatile("ldmatrix.sync.aligned.m8n8.x4.shared.b16 {%0,%1,%2,%3}, [%4];" \
                 : "=r"(r0), "=r"(r1), "=r"(r2), "=r"(r3) : "r"(addr))
#define LDSM_X4_T(r0, r1, r2, r3, addr) \
    asm volatile("ldmatrix.sync.aligned.m8n8.x4.trans.shared.b16 {%0,%1,%2,%3}, [%4];" \
                 : "=r"(r0), "=r"(r1), "=r"(r2), "=r"(r3) : "r"(addr))

#define MMA_F16(c, a, b) \
    asm volatile("mma.sync.aligned.m16n8k16.row.col.f32.f16.f16.f32 " \
                 "{%0,%1,%2,%3},{%4,%5,%6,%7},{%8,%9},{%0,%1,%2,%3};" \
                 : "+f"((c)[0]), "+f"((c)[1]), "+f"((c)[2]), "+f"((c)[3]) \
                 : "r"((a)[0]), "r"((a)[1]), "r"((a)[2]), "r"((a)[3]), \
                   "r"((b)[0]), "r"((b)[1]))

__device__ __forceinline__ float fast_ex2(float x) {
    float y; asm("ex2.approx.f32 %0, %1;" : "=f"(y) : "f"(x)); return y;
}

// pack two fp32 into f16x2 hi word + f16x2 residual word (22-bit effective)
__device__ __forceinline__ void pack_hilo(float a, float b, uint32_t& h, uint32_t& l) {
    __half2 hv = __floats2half2_rn(a, b);           // .x=a (low 16), .y=b (high 16)
    float2 fv = __half22float2(hv);
    __half2 lv = __floats2half2_rn(a - fv.x, b - fv.y);
    h = *reinterpret_cast<uint32_t*>(&hv);
    l = *reinterpret_cast<uint32_t*>(&lv);
}
__device__ __forceinline__ uint32_t pack_f16(float a, float b) {
    __half2 hv = __floats2half2_rn(a, b);
    return *reinterpret_cast<uint32_t*>(&hv);
}

// ---------------------------------------------------------------------------
// converts
// ---------------------------------------------------------------------------
__global__ __launch_bounds__(256) void split_x(const float* __restrict__ x) {
    int i = blockIdx.x * blockDim.x + threadIdx.x;
    float4 v = ((const float4*)x)[i];
    uint32_t h0, l0, h1, l1;
    pack_hilo(v.x, v.y, h0, l0);
    pack_hilo(v.z, v.w, h1, l1);
    ((uint2*)g_xhi)[i] = make_uint2(h0, h1);
    ((uint2*)g_xlo)[i] = make_uint2(l0, l1);
}

__global__ __launch_bounds__(256) void conv_w(const float* __restrict__ Wq,
                                              const float* __restrict__ Wk,
                                              const float* __restrict__ Wv,
                                              const float* __restrict__ Wo) {
    int i = blockIdx.x * blockDim.x + threadIdx.x;
    int z = blockIdx.z;
    const float* src = (z == 0) ? Wq : (z == 1) ? Wk : (z == 2) ? Wv : Wo;
    unsigned short* dst = (z == 0) ? g_wq : (z == 1) ? g_wk : (z == 2) ? g_wv : g_wo;
    float4 v = ((const float4*)src)[i];
    ((uint2*)dst)[i] = make_uint2(pack_f16(v.x, v.y), pack_f16(v.z, v.w));
}

// ---------------------------------------------------------------------------
// GEMM core: C[256x128 tile] = A[M,K] * B[N,K]^T, fp16 2-pass (A hi/lo, B single).
// 512 threads, 16 warps, warp tile 32x64. K-chunks of 64, double buffered.
// OUT_MODE: 0 = fp32 C, 1 = hi/lo fp16 pair, 2 = single fp16.
// ---------------------------------------------------------------------------
#define GROWB 144
#define AT_B (256 * GROWB)             // 36864
#define BT_B (128 * GROWB)             // 18432
#define G2_STAGE (2 * AT_B + BT_B)     // 92160
#define G2_SMEM (2 * G2_STAGE)         // 184320

__device__ __forceinline__ void gemm_issue2(
    uint32_t sbase, int buf, int tid,
    const unsigned short* __restrict__ Ahi, const unsigned short* __restrict__ Alo,
    const unsigned short* __restrict__ B,
    int rowBase, int colBase, int ch)
{
    const size_t kOff = (size_t)ch * 64;
    const uint32_t stage = sbase + buf * G2_STAGE;
    const unsigned short* a0 = Ahi + (size_t)rowBase * Dmodel + kOff;
    const unsigned short* a1 = Alo + (size_t)rowBase * Dmodel + kOff;
    const unsigned short* b0 = B + (size_t)colBase * Dmodel + kOff;
#pragma unroll
    for (int it = 0; it < 4; it++) {
        int idx = it * 512 + tid; int r = idx >> 3, j = idx & 7;
        CP_ASYNC16(stage + r * GROWB + j * 16, a0 + (size_t)r * Dmodel + j * 8);
    }
#pragma unroll
    for (int it = 0; it < 4; it++) {
        int idx = it * 512 + tid; int r = idx >> 3, j = idx & 7;
        CP_ASYNC16(stage + AT_B + r * GROWB + j * 16, a1 + (size_t)r * Dmodel + j * 8);
    }
#pragma unroll
    for (int it = 0; it < 2; it++) {
        int idx = it * 512 + tid; int r = idx >> 3, j = idx & 7;
        CP_ASYNC16(stage + 2 * AT_B + r * GROWB + j * 16, b0 + (size_t)r * Dmodel + j * 8);
    }
    CP_COMMIT();
}

__device__ __forceinline__ void gemm_core(
    const unsigned short* __restrict__ Ahi, const unsigned short* __restrict__ Alo,
    const unsigned short* __restrict__ B,
    float* __restrict__ C, unsigned short* __restrict__ Chi, unsigned short* __restrict__ Clo,
    int out_mode)
{
    extern __shared__ char smem[];
    const uint32_t sbase = smem_to_u32(smem);
    const int tid = threadIdx.x;
    const int wid = tid >> 5;
    const int lane = tid & 31;

    const int rowBase = blockIdx.y * 256;
    const int colBase = blockIdx.x * 128;
    const int m0 = (wid & 7) * 32;
    const int n0 = (wid >> 3) * 64;

    const int lr = (lane & 7) + (lane & 8);
    const int lk = (lane >> 4) << 3;

    float acc[2][8][4];
#pragma unroll
    for (int mt = 0; mt < 2; mt++)
#pragma unroll
        for (int nt = 0; nt < 8; nt++)
#pragma unroll
            for (int q = 0; q < 4; q++) acc[mt][nt][q] = 0.f;

    const int nch = Dmodel / 64;
    gemm_issue2(sbase, 0, tid, Ahi, Alo, B, rowBase, colBase, 0);
    gemm_issue2(sbase, 1, tid, Ahi, Alo, B, rowBase, colBase, 1);

    for (int ch = 0; ch < nch; ch++) {
        if (ch == nch - 1) { CP_WAIT0(); } else { CP_WAIT1(); }
        __syncthreads();

        const int buf = ch & 1;
        const uint32_t aHiB = sbase + buf * G2_STAGE;
        const uint32_t aLoB = aHiB + AT_B;
        const uint32_t bB = aHiB + 2 * AT_B;

#pragma unroll
        for (int ks = 0; ks < 4; ks++) {
            const int k0 = ks * 16;
            uint32_t ahi[2][4], alo[2][4];
#pragma unroll
            for (int mt = 0; mt < 2; mt++) {
                uint32_t off = (m0 + mt * 16 + lr) * GROWB + (k0 + lk) * 2;
                LDSM_X4(ahi[mt][0], ahi[mt][1], ahi[mt][2], ahi[mt][3], aHiB + off);
                LDSM_X4(alo[mt][0], alo[mt][1], alo[mt][2], alo[mt][3], aLoB + off);
            }
            uint32_t bf[8][2];
#pragma unroll
            for (int jp = 0; jp < 4; jp++) {
                uint32_t off = (n0 + jp * 16 + lr) * GROWB + (k0 + lk) * 2;
                uint32_t r0, r1, r2, r3;
                LDSM_X4(r0, r1, r2, r3, bB + off);
                bf[2 * jp][0] = r0; bf[2 * jp][1] = r2;
                bf[2 * jp + 1][0] = r1; bf[2 * jp + 1][1] = r3;
            }
#pragma unroll
            for (int mt = 0; mt < 2; mt++)
#pragma unroll
                for (int nt = 0; nt < 8; nt++) MMA_F16(acc[mt][nt], ahi[mt], bf[nt]);
#pragma unroll
            for (int mt = 0; mt < 2; mt++)
#pragma unroll
                for (int nt = 0; nt < 8; nt++) MMA_F16(acc[mt][nt], alo[mt], bf[nt]);
        }
        __syncthreads();
        if (ch + 2 < nch)
            gemm_issue2(sbase, buf, tid, Ahi, Alo, B, rowBase, colBase, ch + 2);
    }

    const int cr = lane >> 2;
    const int cc = (lane & 3) * 2;
#pragma unroll
    for (int mt = 0; mt < 2; mt++) {
#pragma unroll
        for (int nt = 0; nt < 8; nt++) {
            const int row = rowBase + m0 + mt * 16 + cr;
            const int col = colBase + n0 + nt * 8 + cc;
            if (out_mode == 1) {
                uint32_t h, l;
                pack_hilo(acc[mt][nt][0], acc[mt][nt][1], h, l);
                *(uint32_t*)(Chi + (size_t)row * Dmodel + col) = h;
                *(uint32_t*)(Clo + (size_t)row * Dmodel + col) = l;
                pack_hilo(acc[mt][nt][2], acc[mt][nt][3], h, l);
                *(uint32_t*)(Chi + (size_t)(row + 8) * Dmodel + col) = h;
                *(uint32_t*)(Clo + (size_t)(row + 8) * Dmodel + col) = l;
            } else if (out_mode == 2) {
                *(uint32_t*)(Chi + (size_t)row * Dmodel + col) = pack_f16(acc[mt][nt][0], acc[mt][nt][1]);
                *(uint32_t*)(Chi + (size_t)(row + 8) * Dmodel + col) = pack_f16(acc[mt][nt][2], acc[mt][nt][3]);
            } else {
                *(float2*)&C[(size_t)row * Dmodel + col] = make_float2(acc[mt][nt][0], acc[mt][nt][1]);
                *(float2*)&C[(size_t)(row + 8) * Dmodel + col] = make_float2(acc[mt][nt][2], acc[mt][nt][3]);
            }
        }
    }
}

__global__ __launch_bounds__(512) void gemm_qkv() {
    const int z = blockIdx.z;
    const unsigned short* B = (z == 0) ? g_wq : (z == 1) ? g_wk : g_wv;
    unsigned short* ch = (z == 0) ? g_qhi : (z == 1) ? g_khi : g_vhi;
    unsigned short* cl = (z == 0) ? g_qlo : nullptr;
    gemm_core(g_xhi, g_xlo, B, nullptr, ch, cl, (z == 0) ? 1 : 2);
}

__global__ __launch_bounds__(512) void gemm_wo(float* __restrict__ out) {
    gemm_core(g_yhi, g_ylo, g_wo, out, nullptr, nullptr, 0);
}

// ---------------------------------------------------------------------------
// Flash attention, fp16 2-pass: S = (Qhi+Qlo)·Khi, O = (Phi+Plo)·Vhi.
// K/V single fp16 tiles -> half the smem and KV traffic of round 6.
// ---------------------------------------------------------------------------
#define ASTRIDE 272
#define ATILE_B (64 * ASTRIDE)         // 17408
#define ASTAGE_B (2 * ATILE_B)         // 34816: Khi, Vhi
#define ATTN_SMEM (2 * ASTAGE_B)       // 69632 (also exactly fits Q hi+lo staging)

__device__ __forceinline__ void attn_issue_kv(uint32_t sbase, int buf, int tid,
                                              size_t hbase, int kt)
{
    const unsigned short* srcs[2] = {g_khi, g_vhi};
    const uint32_t stage = sbase + buf * ASTAGE_B;
#pragma unroll
    for (int t = 0; t < 2; t++) {
        const unsigned short* src = srcs[t] + hbase + (size_t)(kt * 64) * Dmodel;
        const uint32_t dstT = stage + t * ATILE_B;
#pragma unroll
        for (int it = 0; it < 4; it++) {
            int idx = it * 256 + tid;
            int r = idx >> 4;
            int j = idx & 15;
            CP_ASYNC16(dstT + r * ASTRIDE + j * 16, src + (size_t)r * Dmodel + j * 8);
        }
    }
    CP_COMMIT();
}

__global__ __launch_bounds__(256, 1) void attn_mma()
{
    extern __shared__ char smem[];
    const uint32_t sbase = smem_to_u32(smem);
    const int tid = threadIdx.x;
    const int wid = tid >> 5;
    const int lane = tid & 31;

    const int qt = (gridDim.x - 1) - blockIdx.x;
    const int h = blockIdx.y;
    const int b = blockIdx.z;
    const size_t hbase = ((size_t)b * Sseq) * Dmodel + (size_t)h * HDdim;

    const int lr = (lane & 7) + (lane & 8);
    const int lk = (lane >> 4) << 3;
    const float kExp = 1.4426950408889634f * 0.08838834764831845f;

    // stage Q hi+lo (128 x 128 fp16 each) through smem into register frags
    {
#pragma unroll
        for (int it = 0; it < 8; it++) {
            int idx = it * 256 + tid;
            int r = idx >> 4;
            int j = idx & 15;
            const size_t goff = hbase + (size_t)(qt * 128 + r) * Dmodel + j * 8;
            CP_ASYNC16(sbase + r * ASTRIDE + j * 16, g_qhi + goff);
            CP_ASYNC16(sbase + 128 * ASTRIDE + r * ASTRIDE + j * 16, g_qlo + goff);
        }
        CP_COMMIT(); CP_WAIT0();
        __syncthreads();
    }
    uint32_t qfh[8][4], qfl[8][4];
#pragma unroll
    for (int ks = 0; ks < 8; ks++) {
        uint32_t off = (wid * 16 + lr) * ASTRIDE + (ks * 16 + lk) * 2;
        LDSM_X4(qfh[ks][0], qfh[ks][1], qfh[ks][2], qfh[ks][3], sbase + off);
        LDSM_X4(qfl[ks][0], qfl[ks][1], qfl[ks][2], qfl[ks][3], sbase + 128 * ASTRIDE + off);
    }
    __syncthreads();

    float oacc[16][4];
#pragma unroll
    for (int nt = 0; nt < 16; nt++)
#pragma unroll
        for (int q = 0; q < 4; q++) oacc[nt][q] = 0.f;
    float m0 = -1e30f, m1 = -1e30f, l0 = 0.f, l1 = 0.f;

    const int nkt = 2 * qt + 2;
    attn_issue_kv(sbase, 0, tid, hbase, 0);
    if (nkt > 1) attn_issue_kv(sbase, 1, tid, hbase, 1);

    const int row0 = qt * 128 + wid * 16 + (lane >> 2);

    for (int kt = 0; kt < nkt; kt++) {
        if (kt == nkt - 1) { CP_WAIT0(); } else { CP_WAIT1(); }
        __syncthreads();

        const bool active = (kt * 64) <= (qt * 128 + wid * 16 + 15);
        if (active) {
            const uint32_t stage = sbase + (kt & 1) * ASTAGE_B;
            const uint32_t kB = stage;
            const uint32_t vB = stage + ATILE_B;

            // S = Q K^T, 2-pass
            float sacc[8][4];
#pragma unroll
            for (int nt = 0; nt < 8; nt++)
#pragma unroll
                for (int q = 0; q < 4; q++) sacc[nt][q] = 0.f;
#pragma unroll
            for (int ks = 0; ks < 8; ks++) {
#pragma unroll
                for (int jp = 0; jp < 4; jp++) {
                    uint32_t off = (jp * 16 + lr) * ASTRIDE + (ks * 16 + lk) * 2;
                    uint32_t r0, r1, r2, r3;
                    LDSM_X4(r0, r1, r2, r3, kB + off);
                    uint32_t bh0[2] = {r0, r2}, bh1[2] = {r1, r3};
                    MMA_F16(sacc[2 * jp], qfh[ks], bh0);
                    MMA_F16(sacc[2 * jp + 1], qfh[ks], bh1);
                    MMA_F16(sacc[2 * jp], qfl[ks], bh0);
                    MMA_F16(sacc[2 * jp + 1], qfl[ks], bh1);
                }
            }

            // online softmax (base-2, scale folded), causal mask
            const bool needm = (kt * 64 + 63) > (qt * 128 + wid * 16);
            const int col0 = kt * 64 + 2 * (lane & 3);
            float mx0 = -1e30f, mx1 = -1e30f;
#pragma unroll
            for (int nt = 0; nt < 8; nt++) {
#pragma unroll
                for (int e = 0; e < 2; e++) {
                    float v = sacc[nt][e] * kExp;
                    if (needm && (col0 + nt * 8 + e > row0)) v = -1e30f;
                    sacc[nt][e] = v;
                    mx0 = fmaxf(mx0, v);
                    float w = sacc[nt][2 + e] * kExp;
                    if (needm && (col0 + nt * 8 + e > row0 + 8)) w = -1e30f;
                    sacc[nt][2 + e] = w;
                    mx1 = fmaxf(mx1, w);
                }
            }
            mx0 = fmaxf(mx0, __shfl_xor_sync(0xffffffffu, mx0, 1));
            mx0 = fmaxf(mx0, __shfl_xor_sync(0xffffffffu, mx0, 2));
            mx1 = fmaxf(mx1, __shfl_xor_sync(0xffffffffu, mx1, 1));
            mx1 = fmaxf(mx1, __shfl_xor_sync(0xffffffffu, mx1, 2));
            float mn0 = fmaxf(m0, mx0), mn1 = fmaxf(m1, mx1);
            float a0 = fast_ex2(m0 - mn0), a1 = fast_ex2(m1 - mn1);
#pragma unroll
            for (int nt = 0; nt < 16; nt++) {
                oacc[nt][0] *= a0; oacc[nt][1] *= a0;
                oacc[nt][2] *= a1; oacc[nt][3] *= a1;
            }
            float ls0 = 0.f, ls1 = 0.f;
#pragma unroll
            for (int nt = 0; nt < 8; nt++) {
#pragma unroll
                for (int e = 0; e < 2; e++) {
                    float p0 = fast_ex2(sacc[nt][e] - mn0);
                    float p1 = fast_ex2(sacc[nt][2 + e] - mn1);
                    sacc[nt][e] = p0; sacc[nt][2 + e] = p1;
                    ls0 += p0; ls1 += p1;
                }
            }
            ls0 += __shfl_xor_sync(0xffffffffu, ls0, 1);
            ls0 += __shfl_xor_sync(0xffffffffu, ls0, 2);
            ls1 += __shfl_xor_sync(0xffffffffu, ls1, 1);
            ls1 += __shfl_xor_sync(0xffffffffu, ls1, 2);
            l0 = l0 * a0 + ls0; l1 = l1 * a1 + ls1;
            m0 = mn0; m1 = mn1;

            // O += P V, 2-pass
#pragma unroll
            for (int kstep = 0; kstep < 4; kstep++) {
                uint32_t ph[4], pl[4];
                pack_hilo(sacc[2 * kstep][0], sacc[2 * kstep][1], ph[0], pl[0]);
                pack_hilo(sacc[2 * kstep][2], sacc[2 * kstep][3], ph[1], pl[1]);
                pack_hilo(sacc[2 * kstep + 1][0], sacc[2 * kstep + 1][1], ph[2], pl[2]);
                pack_hilo(sacc[2 * kstep + 1][2], sacc[2 * kstep + 1][3], ph[3], pl[3]);
#pragma unroll
                for (int dp = 0; dp < 8; dp++) {
                    uint32_t off = (kstep * 16 + lr) * ASTRIDE + (dp * 16 + lk) * 2;
                    uint32_t v0, v1, v2, v3;
                    LDSM_X4_T(v0, v1, v2, v3, vB + off);
                    uint32_t bh0[2] = {v0, v1}, bh1[2] = {v2, v3};
                    MMA_F16(oacc[2 * dp], ph, bh0);
                    MMA_F16(oacc[2 * dp + 1], ph, bh1);
                    MMA_F16(oacc[2 * dp], pl, bh0);
                    MMA_F16(oacc[2 * dp + 1], pl, bh1);
                }
            }
        }
        __syncthreads();
        if (kt + 2 < nkt)
            attn_issue_kv(sbase, kt & 1, tid, hbase, kt + 2);
    }

    const float inv0 = 1.f / l0;
    const float inv1 = 1.f / l1;
#pragma unroll
    for (int nt = 0; nt < 16; nt++) {
        const int col = nt * 8 + 2 * (lane & 3);
        const size_t i0 = ((size_t)b * Sseq + row0) * Dmodel + h * HDdim + col;
        const size_t i1 = ((size_t)b * Sseq + row0 + 8) * Dmodel + h * HDdim + col;
        uint32_t hh, ll;
        pack_hilo(oacc[nt][0] * inv0, oacc[nt][1] * inv0, hh, ll);
        *(uint32_t*)(g_yhi + i0) = hh;
        *(uint32_t*)(g_ylo + i0) = ll;
        pack_hilo(oacc[nt][2] * inv1, oacc[nt][3] * inv1, hh, ll);
        *(uint32_t*)(g_yhi + i1) = hh;
        *(uint32_t*)(g_ylo + i1) = ll;
    }
}

// ---------------------------------------------------------------------------
// launch
// ---------------------------------------------------------------------------
extern "C" void kernel_launch(void* const* d_in, const int* in_sizes, int n_in,
                              void* d_out, int out_size)
{
    (void)in_sizes; (void)n_in; (void)out_size;
    const float* x  = (const float*)d_in[0];
    const float* Wq = (const float*)d_in[2];
    const float* Wk = (const float*)d_in[3];
    const float* Wv = (const float*)d_in[4];
    const float* Wo = (const float*)d_in[5];
    float* out = (float*)d_out;

    cudaFuncSetAttribute(gemm_qkv, cudaFuncAttributeMaxDynamicSharedMemorySize, G2_SMEM);
    cudaFuncSetAttribute(gemm_wo, cudaFuncAttributeMaxDynamicSharedMemorySize, G2_SMEM);
    cudaFuncSetAttribute(attn_mma, cudaFuncAttributeMaxDynamicSharedMemorySize, ATTN_SMEM);

    const int nX4 = Mrows * Dmodel / 4;
    const int nW4 = Dmodel * Dmodel / 4;

    split_x<<<nX4 / 256, 256>>>(x);
    conv_w<<<dim3(nW4 / 256, 1, 4), 256>>>(Wq, Wk, Wv, Wo);

    gemm_qkv<<<dim3(Dmodel / 128, Mrows / 256, 3), 512, G2_SMEM>>>();
    attn_mma<<<dim3(Sseq / 128, Hheads, Bsz), 256, ATTN_SMEM>>>();
    gemm_wo<<<dim3(Dmodel / 128, Mrows / 256, 1), 512, G2_SMEM>>>(out);
}

// round 8
// speedup vs baseline: 4.1880x; 1.0967x over previous
#include <cuda_runtime.h>
#include <cuda_fp16.h>
#include <math.h>
#include <stdint.h>

#define Bsz 2
#define Sseq 2048
#define Dmodel 2048
#define Hheads 16
#define HDdim 128
#define Mrows (Bsz * Sseq)   // 4096

// ---------------- scratch (fp16 payloads in ushort arrays) ----------------
__device__ unsigned short g_xhi[Mrows * Dmodel];
__device__ unsigned short g_xlo[Mrows * Dmodel];
__device__ unsigned short g_qhi[Mrows * Dmodel];
__device__ unsigned short g_qlo[Mrows * Dmodel];
__device__ unsigned short g_khi[Mrows * Dmodel];
__device__ unsigned short g_vhi[Mrows * Dmodel];
__device__ unsigned short g_yhi[Mrows * Dmodel];
__device__ unsigned short g_ylo[Mrows * Dmodel];
__device__ unsigned short g_wq[Dmodel * Dmodel];
__device__ unsigned short g_wk[Dmodel * Dmodel];
__device__ unsigned short g_wv[Dmodel * Dmodel];
__device__ unsigned short g_wo[Dmodel * Dmodel];

// ---------------- helpers ----------------
__device__ __forceinline__ uint32_t smem_to_u32(const void* p) {
    uint32_t a;
    asm("{ .reg .u64 t; cvta.to.shared.u64 t, %1; cvt.u32.u64 %0, t; }" : "=r"(a) : "l"(p));
    return a;
}

#define CP_ASYNC16(dst_u32, src_ptr) \
    asm volatile("cp.async.cg.shared.global [%0], [%1], 16;" :: "r"(dst_u32), "l"(src_ptr))
#define CP_COMMIT() asm volatile("cp.async.commit_group;")
#define CP_WAIT1()  asm volatile("cp.async.wait_group 1;")
#define CP_WAIT0()  asm volatile("cp.async.wait_group 0;")

#define LDSM_X4(r0, r1, r2, r3, addr) \
    asm volatile("ldmatrix.sync.aligned.m8n8.x4.shared.b16 {%0,%1,%2,%3}, [%4];" \
                 : "=r"(r0), "=r"(r1), "=r"(r2), "=r"(r3) : "r"(addr))
#define LDSM_X4_T(r0, r1, r2, r3, addr) \
    asm volatile("ldmatrix.sync.aligned.m8n8.x4.trans.shared.b16 {%0,%1,%2,%3}, [%4];" \
                 : "=r"(r0), "=r"(r1), "=r"(r2), "=r"(r3) : "r"(addr))

#define MMA_F16(c, a, b) \
    asm volatile("mma.sync.aligned.m16n8k16.row.col.f32.f16.f16.f32 " \
                 "{%0,%1,%2,%3},{%4,%5,%6,%7},{%8,%9},{%0,%1,%2,%3};" \
                 : "+f"((c)[0]), "+f"((c)[1]), "+f"((c)[2]), "+f"((c)[3]) \
                 : "r"((a)[0]), "r"((a)[1]), "r"((a)[2]), "r"((a)[3]), \
                   "r"((b)[0]), "r"((b)[1]))

__device__ __forceinline__ float fast_ex2(float x) {
    float y; asm("ex2.approx.f32 %0, %1;" : "=f"(y) : "f"(x)); return y;
}

__device__ __forceinline__ void pack_hilo(float a, float b, uint32_t& h, uint32_t& l) {
    __half2 hv = __floats2half2_rn(a, b);
    float2 fv = __half22float2(hv);
    __half2 lv = __floats2half2_rn(a - fv.x, b - fv.y);
    h = *reinterpret_cast<uint32_t*>(&hv);
    l = *reinterpret_cast<uint32_t*>(&lv);
}
__device__ __forceinline__ uint32_t pack_f16(float a, float b) {
    __half2 hv = __floats2half2_rn(a, b);
    return *reinterpret_cast<uint32_t*>(&hv);
}

// ---------------------------------------------------------------------------
// converts
// ---------------------------------------------------------------------------
__global__ __launch_bounds__(256) void split_x(const float* __restrict__ x) {
    int i = blockIdx.x * blockDim.x + threadIdx.x;
    float4 v = ((const float4*)x)[i];
    uint32_t h0, l0, h1, l1;
    pack_hilo(v.x, v.y, h0, l0);
    pack_hilo(v.z, v.w, h1, l1);
    ((uint2*)g_xhi)[i] = make_uint2(h0, h1);
    ((uint2*)g_xlo)[i] = make_uint2(l0, l1);
}

__global__ __launch_bounds__(256) void conv_w(const float* __restrict__ Wq,
                                              const float* __restrict__ Wk,
                                              const float* __restrict__ Wv,
                                              const float* __restrict__ Wo) {
    int i = blockIdx.x * blockDim.x + threadIdx.x;
    int z = blockIdx.z;
    const float* src = (z == 0) ? Wq : (z == 1) ? Wk : (z == 2) ? Wv : Wo;
    unsigned short* dst = (z == 0) ? g_wq : (z == 1) ? g_wk : (z == 2) ? g_wv : g_wo;
    float4 v = ((const float4*)src)[i];
    ((uint2*)dst)[i] = make_uint2(pack_f16(v.x, v.y), pack_f16(v.z, v.w));
}

// ---------------------------------------------------------------------------
// GEMM: C[128x128 tile] = A[M,K] * B[N,K]^T, fp16 2-pass (A hi/lo, B single).
// 256 threads, 8 warps (4 row x 2 col groups), warp tile 32x64.
// K-chunks of 64, double buffer; smem 110.6 KB -> 2 CTAs/SM for overlap.
// ---------------------------------------------------------------------------
#define GROWB 144
#define TILE_B (128 * GROWB)           // 18432
#define STAGE_B (3 * TILE_B)           // 55296: Ahi, Alo, B
#define G_SMEM (2 * STAGE_B)           // 110592

__device__ __forceinline__ void gemm_issue(
    uint32_t sbase, int buf, int tid,
    const unsigned short* __restrict__ Ahi, const unsigned short* __restrict__ Alo,
    const unsigned short* __restrict__ B,
    int rowBase, int colBase, int ch)
{
    const size_t kOff = (size_t)ch * 64;
    const uint32_t stage = sbase + buf * STAGE_B;
    const unsigned short* srcs[3] = {
        Ahi + (size_t)rowBase * Dmodel + kOff,
        Alo + (size_t)rowBase * Dmodel + kOff,
        B   + (size_t)colBase * Dmodel + kOff };
#pragma unroll
    for (int t = 0; t < 3; t++) {
        const unsigned short* src = srcs[t];
        const uint32_t dstT = stage + t * TILE_B;
#pragma unroll
        for (int it = 0; it < 4; it++) {
            int idx = it * 256 + tid;   // 0..1023
            int r = idx >> 3;           // row 0..127
            int j = idx & 7;            // 16B chunk
            CP_ASYNC16(dstT + r * GROWB + j * 16, src + (size_t)r * Dmodel + j * 8);
        }
    }
    CP_COMMIT();
}

__device__ __forceinline__ void gemm_core(
    const unsigned short* __restrict__ Ahi, const unsigned short* __restrict__ Alo,
    const unsigned short* __restrict__ B,
    float* __restrict__ C, unsigned short* __restrict__ Chi, unsigned short* __restrict__ Clo,
    int out_mode)
{
    extern __shared__ char smem[];
    const uint32_t sbase = smem_to_u32(smem);
    const int tid = threadIdx.x;
    const int wid = tid >> 5;
    const int lane = tid & 31;

    const int rowBase = blockIdx.y * 128;
    const int colBase = blockIdx.x * 128;
    const int m0 = (wid & 3) * 32;
    const int n0 = (wid >> 2) * 64;

    const int lr = (lane & 7) + (lane & 8);
    const int lk = (lane >> 4) << 3;

    float acc[2][8][4];
#pragma unroll
    for (int mt = 0; mt < 2; mt++)
#pragma unroll
        for (int nt = 0; nt < 8; nt++)
#pragma unroll
            for (int q = 0; q < 4; q++) acc[mt][nt][q] = 0.f;

    const int nch = Dmodel / 64;   // 32
    gemm_issue(sbase, 0, tid, Ahi, Alo, B, rowBase, colBase, 0);
    gemm_issue(sbase, 1, tid, Ahi, Alo, B, rowBase, colBase, 1);

    for (int ch = 0; ch < nch; ch++) {
        if (ch == nch - 1) { CP_WAIT0(); } else { CP_WAIT1(); }
        __syncthreads();

        const int buf = ch & 1;
        const uint32_t aHiB = sbase + buf * STAGE_B;
        const uint32_t aLoB = aHiB + TILE_B;
        const uint32_t bB = aHiB + 2 * TILE_B;

#pragma unroll
        for (int ks = 0; ks < 4; ks++) {
            const int k0 = ks * 16;
            uint32_t ahi[2][4], alo[2][4];
#pragma unroll
            for (int mt = 0; mt < 2; mt++) {
                uint32_t off = (m0 + mt * 16 + lr) * GROWB + (k0 + lk) * 2;
                LDSM_X4(ahi[mt][0], ahi[mt][1], ahi[mt][2], ahi[mt][3], aHiB + off);
                LDSM_X4(alo[mt][0], alo[mt][1], alo[mt][2], alo[mt][3], aLoB + off);
            }
            uint32_t bf[8][2];
#pragma unroll
            for (int jp = 0; jp < 4; jp++) {
                uint32_t off = (n0 + jp * 16 + lr) * GROWB + (k0 + lk) * 2;
                uint32_t r0, r1, r2, r3;
                LDSM_X4(r0, r1, r2, r3, bB + off);
                bf[2 * jp][0] = r0; bf[2 * jp][1] = r2;
                bf[2 * jp + 1][0] = r1; bf[2 * jp + 1][1] = r3;
            }
#pragma unroll
            for (int mt = 0; mt < 2; mt++)
#pragma unroll
                for (int nt = 0; nt < 8; nt++) MMA_F16(acc[mt][nt], ahi[mt], bf[nt]);
#pragma unroll
            for (int mt = 0; mt < 2; mt++)
#pragma unroll
                for (int nt = 0; nt < 8; nt++) MMA_F16(acc[mt][nt], alo[mt], bf[nt]);
        }
        __syncthreads();
        if (ch + 2 < nch)
            gemm_issue(sbase, buf, tid, Ahi, Alo, B, rowBase, colBase, ch + 2);
    }

    const int cr = lane >> 2;
    const int cc = (lane & 3) * 2;
#pragma unroll
    for (int mt = 0; mt < 2; mt++) {
#pragma unroll
        for (int nt = 0; nt < 8; nt++) {
            const int row = rowBase + m0 + mt * 16 + cr;
            const int col = colBase + n0 + nt * 8 + cc;
            if (out_mode == 1) {
                uint32_t h, l;
                pack_hilo(acc[mt][nt][0], acc[mt][nt][1], h, l);
                *(uint32_t*)(Chi + (size_t)row * Dmodel + col) = h;
                *(uint32_t*)(Clo + (size_t)row * Dmodel + col) = l;
                pack_hilo(acc[mt][nt][2], acc[mt][nt][3], h, l);
                *(uint32_t*)(Chi + (size_t)(row + 8) * Dmodel + col) = h;
                *(uint32_t*)(Clo + (size_t)(row + 8) * Dmodel + col) = l;
            } else if (out_mode == 2) {
                *(uint32_t*)(Chi + (size_t)row * Dmodel + col) = pack_f16(acc[mt][nt][0], acc[mt][nt][1]);
                *(uint32_t*)(Chi + (size_t)(row + 8) * Dmodel + col) = pack_f16(acc[mt][nt][2], acc[mt][nt][3]);
            } else {
                *(float2*)&C[(size_t)row * Dmodel + col] = make_float2(acc[mt][nt][0], acc[mt][nt][1]);
                *(float2*)&C[(size_t)(row + 8) * Dmodel + col] = make_float2(acc[mt][nt][2], acc[mt][nt][3]);
            }
        }
    }
}

__global__ __launch_bounds__(256, 2) void gemm_qkv() {
    const int z = blockIdx.z;
    const unsigned short* B = (z == 0) ? g_wq : (z == 1) ? g_wk : g_wv;
    unsigned short* ch = (z == 0) ? g_qhi : (z == 1) ? g_khi : g_vhi;
    unsigned short* cl = (z == 0) ? g_qlo : nullptr;
    gemm_core(g_xhi, g_xlo, B, nullptr, ch, cl, (z == 0) ? 1 : 2);
}

__global__ __launch_bounds__(256, 2) void gemm_wo(float* __restrict__ out) {
    gemm_core(g_yhi, g_ylo, g_wo, out, nullptr, nullptr, 0);
}

// ---------------------------------------------------------------------------
// Flash attention, fp16 2-pass, pass-separated MMA ordering.
// ---------------------------------------------------------------------------
#define ASTRIDE 272
#define ATILE_B (64 * ASTRIDE)         // 17408
#define ASTAGE_B (2 * ATILE_B)         // 34816: Khi, Vhi
#define ATTN_SMEM (2 * ASTAGE_B)       // 69632

__device__ __forceinline__ void attn_issue_kv(uint32_t sbase, int buf, int tid,
                                              size_t hbase, int kt)
{
    const unsigned short* srcs[2] = {g_khi, g_vhi};
    const uint32_t stage = sbase + buf * ASTAGE_B;
#pragma unroll
    for (int t = 0; t < 2; t++) {
        const unsigned short* src = srcs[t] + hbase + (size_t)(kt * 64) * Dmodel;
        const uint32_t dstT = stage + t * ATILE_B;
#pragma unroll
        for (int it = 0; it < 4; it++) {
            int idx = it * 256 + tid;
            int r = idx >> 4;
            int j = idx & 15;
            CP_ASYNC16(dstT + r * ASTRIDE + j * 16, src + (size_t)r * Dmodel + j * 8);
        }
    }
    CP_COMMIT();
}

__global__ __launch_bounds__(256, 1) void attn_mma()
{
    extern __shared__ char smem[];
    const uint32_t sbase = smem_to_u32(smem);
    const int tid = threadIdx.x;
    const int wid = tid >> 5;
    const int lane = tid & 31;

    const int qt = (gridDim.x - 1) - blockIdx.x;
    const int h = blockIdx.y;
    const int b = blockIdx.z;
    const size_t hbase = ((size_t)b * Sseq) * Dmodel + (size_t)h * HDdim;

    const int lr = (lane & 7) + (lane & 8);
    const int lk = (lane >> 4) << 3;
    const float kExp = 1.4426950408889634f * 0.08838834764831845f;

    {
#pragma unroll
        for (int it = 0; it < 8; it++) {
            int idx = it * 256 + tid;
            int r = idx >> 4;
            int j = idx & 15;
            const size_t goff = hbase + (size_t)(qt * 128 + r) * Dmodel + j * 8;
            CP_ASYNC16(sbase + r * ASTRIDE + j * 16, g_qhi + goff);
            CP_ASYNC16(sbase + 128 * ASTRIDE + r * ASTRIDE + j * 16, g_qlo + goff);
        }
        CP_COMMIT(); CP_WAIT0();
        __syncthreads();
    }
    uint32_t qfh[8][4], qfl[8][4];
#pragma unroll
    for (int ks = 0; ks < 8; ks++) {
        uint32_t off = (wid * 16 + lr) * ASTRIDE + (ks * 16 + lk) * 2;
        LDSM_X4(qfh[ks][0], qfh[ks][1], qfh[ks][2], qfh[ks][3], sbase + off);
        LDSM_X4(qfl[ks][0], qfl[ks][1], qfl[ks][2], qfl[ks][3], sbase + 128 * ASTRIDE + off);
    }
    __syncthreads();

    float oacc[16][4];
#pragma unroll
    for (int nt = 0; nt < 16; nt++)
#pragma unroll
        for (int q = 0; q < 4; q++) oacc[nt][q] = 0.f;
    float m0 = -1e30f, m1 = -1e30f, l0 = 0.f, l1 = 0.f;

    const int nkt = 2 * qt + 2;
    attn_issue_kv(sbase, 0, tid, hbase, 0);
    if (nkt > 1) attn_issue_kv(sbase, 1, tid, hbase, 1);

    const int row0 = qt * 128 + wid * 16 + (lane >> 2);

    for (int kt = 0; kt < nkt; kt++) {
        if (kt == nkt - 1) { CP_WAIT0(); } else { CP_WAIT1(); }
        __syncthreads();

        const bool active = (kt * 64) <= (qt * 128 + wid * 16 + 15);
        if (active) {
            const uint32_t stage = sbase + (kt & 1) * ASTAGE_B;
            const uint32_t kB = stage;
            const uint32_t vB = stage + ATILE_B;

            // S = Q K^T: per-ks, load all K frags, then hi pass, then lo pass
            float sacc[8][4];
#pragma unroll
            for (int nt = 0; nt < 8; nt++)
#pragma unroll
                for (int q = 0; q < 4; q++) sacc[nt][q] = 0.f;
#pragma unroll
            for (int ks = 0; ks < 8; ks++) {
                uint32_t bh[8][2];
#pragma unroll
                for (int jp = 0; jp < 4; jp++) {
                    uint32_t off = (jp * 16 + lr) * ASTRIDE + (ks * 16 + lk) * 2;
                    uint32_t r0, r1, r2, r3;
                    LDSM_X4(r0, r1, r2, r3, kB + off);
                    bh[2 * jp][0] = r0; bh[2 * jp][1] = r2;
                    bh[2 * jp + 1][0] = r1; bh[2 * jp + 1][1] = r3;
                }
#pragma unroll
                for (int nt = 0; nt < 8; nt++) MMA_F16(sacc[nt], qfh[ks], bh[nt]);
#pragma unroll
                for (int nt = 0; nt < 8; nt++) MMA_F16(sacc[nt], qfl[ks], bh[nt]);
            }

            // online softmax (base-2, scale folded), causal mask
            const bool needm = (kt * 64 + 63) > (qt * 128 + wid * 16);
            const int col0 = kt * 64 + 2 * (lane & 3);
            float mx0 = -1e30f, mx1 = -1e30f;
#pragma unroll
            for (int nt = 0; nt < 8; nt++) {
#pragma unroll
                for (int e = 0; e < 2; e++) {
                    float v = sacc[nt][e] * kExp;
                    if (needm && (col0 + nt * 8 + e > row0)) v = -1e30f;
                    sacc[nt][e] = v;
                    mx0 = fmaxf(mx0, v);
                    float w = sacc[nt][2 + e] * kExp;
                    if (needm && (col0 + nt * 8 + e > row0 + 8)) w = -1e30f;
                    sacc[nt][2 + e] = w;
                    mx1 = fmaxf(mx1, w);
                }
            }
            mx0 = fmaxf(mx0, __shfl_xor_sync(0xffffffffu, mx0, 1));
            mx0 = fmaxf(mx0, __shfl_xor_sync(0xffffffffu, mx0, 2));
            mx1 = fmaxf(mx1, __shfl_xor_sync(0xffffffffu, mx1, 1));
            mx1 = fmaxf(mx1, __shfl_xor_sync(0xffffffffu, mx1, 2));
            float mn0 = fmaxf(m0, mx0), mn1 = fmaxf(m1, mx1);
            float a0 = fast_ex2(m0 - mn0), a1 = fast_ex2(m1 - mn1);
#pragma unroll
            for (int nt = 0; nt < 16; nt++) {
                oacc[nt][0] *= a0; oacc[nt][1] *= a0;
                oacc[nt][2] *= a1; oacc[nt][3] *= a1;
            }
            float ls0 = 0.f, ls1 = 0.f;
#pragma unroll
            for (int nt = 0; nt < 8; nt++) {
#pragma unroll
                for (int e = 0; e < 2; e++) {
                    float p0 = fast_ex2(sacc[nt][e] - mn0);
                    float p1 = fast_ex2(sacc[nt][2 + e] - mn1);
                    sacc[nt][e] = p0; sacc[nt][2 + e] = p1;
                    ls0 += p0; ls1 += p1;
                }
            }
            ls0 += __shfl_xor_sync(0xffffffffu, ls0, 1);
            ls0 += __shfl_xor_sync(0xffffffffu, ls0, 2);
            ls1 += __shfl_xor_sync(0xffffffffu, ls1, 1);
            ls1 += __shfl_xor_sync(0xffffffffu, ls1, 2);
            l0 = l0 * a0 + ls0; l1 = l1 * a1 + ls1;
            m0 = mn0; m1 = mn1;

            // O += P V: per-kstep, dp-blocks of 4; ph pass then pl pass
#pragma unroll
            for (int kstep = 0; kstep < 4; kstep++) {
                uint32_t ph[4], pl[4];
                pack_hilo(sacc[2 * kstep][0], sacc[2 * kstep][1], ph[0], pl[0]);
                pack_hilo(sacc[2 * kstep][2], sacc[2 * kstep][3], ph[1], pl[1]);
                pack_hilo(sacc[2 * kstep + 1][0], sacc[2 * kstep + 1][1], ph[2], pl[2]);
                pack_hilo(sacc[2 * kstep + 1][2], sacc[2 * kstep + 1][3], ph[3], pl[3]);
#pragma unroll
                for (int db = 0; db < 2; db++) {
                    uint32_t bv[8][2];
#pragma unroll
                    for (int dpi = 0; dpi < 4; dpi++) {
                        const int dp = db * 4 + dpi;
                        uint32_t off = (kstep * 16 + lr) * ASTRIDE + (dp * 16 + lk) * 2;
                        uint32_t v0, v1, v2, v3;
                        LDSM_X4_T(v0, v1, v2, v3, vB + off);
                        bv[2 * dpi][0] = v0; bv[2 * dpi][1] = v1;
                        bv[2 * dpi + 1][0] = v2; bv[2 * dpi + 1][1] = v3;
                    }
#pragma unroll
                    for (int dpi = 0; dpi < 4; dpi++) {
                        MMA_F16(oacc[2 * (db * 4 + dpi)], ph, bv[2 * dpi]);
                        MMA_F16(oacc[2 * (db * 4 + dpi) + 1], ph, bv[2 * dpi + 1]);
                    }
#pragma unroll
                    for (int dpi = 0; dpi < 4; dpi++) {
                        MMA_F16(oacc[2 * (db * 4 + dpi)], pl, bv[2 * dpi]);
                        MMA_F16(oacc[2 * (db * 4 + dpi) + 1], pl, bv[2 * dpi + 1]);
                    }
                }
            }
        }
        __syncthreads();
        if (kt + 2 < nkt)
            attn_issue_kv(sbase, kt & 1, tid, hbase, kt + 2);
    }

    const float inv0 = 1.f / l0;
    const float inv1 = 1.f / l1;
#pragma unroll
    for (int nt = 0; nt < 16; nt++) {
        const int col = nt * 8 + 2 * (lane & 3);
        const size_t i0 = ((size_t)b * Sseq + row0) * Dmodel + h * HDdim + col;
        const size_t i1 = ((size_t)b * Sseq + row0 + 8) * Dmodel + h * HDdim + col;
        uint32_t hh, ll;
        pack_hilo(oacc[nt][0] * inv0, oacc[nt][1] * inv0, hh, ll);
        *(uint32_t*)(g_yhi + i0) = hh;
        *(uint32_t*)(g_ylo + i0) = ll;
        pack_hilo(oacc[nt][2] * inv1, oacc[nt][3] * inv1, hh, ll);
        *(uint32_t*)(g_yhi + i1) = hh;
        *(uint32_t*)(g_ylo + i1) = ll;
    }
}

// ---------------------------------------------------------------------------
// launch
// ---------------------------------------------------------------------------
extern "C" void kernel_launch(void* const* d_in, const int* in_sizes, int n_in,
                              void* d_out, int out_size)
{
    (void)in_sizes; (void)n_in; (void)out_size;
    const float* x  = (const float*)d_in[0];
    const float* Wq = (const float*)d_in[2];
    const float* Wk = (const float*)d_in[3];
    const float* Wv = (const float*)d_in[4];
    const float* Wo = (const float*)d_in[5];
    float* out = (float*)d_out;

    cudaFuncSetAttribute(gemm_qkv, cudaFuncAttributeMaxDynamicSharedMemorySize, G_SMEM);
    cudaFuncSetAttribute(gemm_wo, cudaFuncAttributeMaxDynamicSharedMemorySize, G_SMEM);
    cudaFuncSetAttribute(attn_mma, cudaFuncAttributeMaxDynamicSharedMemorySize, ATTN_SMEM);

    const int nX4 = Mrows * Dmodel / 4;
    const int nW4 = Dmodel * Dmodel / 4;

    split_x<<<nX4 / 256, 256>>>(x);
    conv_w<<<dim3(nW4 / 256, 1, 4), 256>>>(Wq, Wk, Wv, Wo);

    gemm_qkv<<<dim3(Dmodel / 128, Mrows / 128, 3), 256, G_SMEM>>>();
    attn_mma<<<dim3(Sseq / 128, Hheads, Bsz), 256, ATTN_SMEM>>>();
    gemm_wo<<<dim3(Dmodel / 128, Mrows / 128, 1), 256, G_SMEM>>>(out);
}

// round 9
// speedup vs baseline: 6.0521x; 1.4451x over previous
#include <cuda_runtime.h>
#include <cuda_fp16.h>
#include <math.h>
#include <stdint.h>

#define Bsz 2
#define Sseq 2048
#define Dmodel 2048
#define Hheads 16
#define HDdim 128
#define Mrows (Bsz * Sseq)   // 4096

// ---------------- scratch (fp16 payloads in ushort arrays) ----------------
__device__ unsigned short g_xhi[Mrows * Dmodel];
__device__ unsigned short g_qhi[Mrows * Dmodel];
__device__ unsigned short g_khi[Mrows * Dmodel];
__device__ unsigned short g_vhi[Mrows * Dmodel];
__device__ unsigned short g_yhi[Mrows * Dmodel];
__device__ unsigned short g_ylo[Mrows * Dmodel];
__device__ unsigned short g_wq[Dmodel * Dmodel];
__device__ unsigned short g_wk[Dmodel * Dmodel];
__device__ unsigned short g_wv[Dmodel * Dmodel];
__device__ unsigned short g_wo[Dmodel * Dmodel];

// ---------------- helpers ----------------
__device__ __forceinline__ uint32_t smem_to_u32(const void* p) {
    uint32_t a;
    asm("{ .reg .u64 t; cvta.to.shared.u64 t, %1; cvt.u32.u64 %0, t; }" : "=r"(a) : "l"(p));
    return a;
}

#define CP_ASYNC16(dst_u32, src_ptr) \
    asm volatile("cp.async.cg.shared.global [%0], [%1], 16;" :: "r"(dst_u32), "l"(src_ptr))
#define CP_COMMIT() asm volatile("cp.async.commit_group;")
#define CP_WAIT1()  asm volatile("cp.async.wait_group 1;")
#define CP_WAIT0()  asm volatile("cp.async.wait_group 0;")

#define LDSM_X4(r0, r1, r2, r3, addr) \
    asm volatile("ldmatrix.sync.aligned.m8n8.x4.shared.b16 {%0,%1,%2,%3}, [%4];" \
                 : "=r"(r0), "=r"(r1), "=r"(r2), "=r"(r3) : "r"(addr))
#define LDSM_X4_T(r0, r1, r2, r3, addr) \
    asm volatile("ldmatrix.sync.aligned.m8n8.x4.trans.shared.b16 {%0,%1,%2,%3}, [%4];" \
                 : "=r"(r0), "=r"(r1), "=r"(r2), "=r"(r3) : "r"(addr))

#define MMA_F16(c, a, b) \
    asm volatile("mma.sync.aligned.m16n8k16.row.col.f32.f16.f16.f32 " \
                 "{%0,%1,%2,%3},{%4,%5,%6,%7},{%8,%9},{%0,%1,%2,%3};" \
                 : "+f"((c)[0]), "+f"((c)[1]), "+f"((c)[2]), "+f"((c)[3]) \
                 : "r"((a)[0]), "r"((a)[1]), "r"((a)[2]), "r"((a)[3]), \
                   "r"((b)[0]), "r"((b)[1]))

__device__ __forceinline__ float fast_ex2(float x) {
    float y; asm("ex2.approx.f32 %0, %1;" : "=f"(y) : "f"(x)); return y;
}

__device__ __forceinline__ void pack_hilo(float a, float b, uint32_t& h, uint32_t& l) {
    __half2 hv = __floats2half2_rn(a, b);
    float2 fv = __half22float2(hv);
    __half2 lv = __floats2half2_rn(a - fv.x, b - fv.y);
    h = *reinterpret_cast<uint32_t*>(&hv);
    l = *reinterpret_cast<uint32_t*>(&lv);
}
__device__ __forceinline__ uint32_t pack_f16(float a, float b) {
    __half2 hv = __floats2half2_rn(a, b);
    return *reinterpret_cast<uint32_t*>(&hv);
}

// ---------------------------------------------------------------------------
// converts: fp32 -> fp16
// ---------------------------------------------------------------------------
__global__ __launch_bounds__(256) void conv_x(const float* __restrict__ x) {
    int i = blockIdx.x * blockDim.x + threadIdx.x;
    float4 v = ((const float4*)x)[i];
    ((uint2*)g_xhi)[i] = make_uint2(pack_f16(v.x, v.y), pack_f16(v.z, v.w));
}

__global__ __launch_bounds__(256) void conv_w(const float* __restrict__ Wq,
                                              const float* __restrict__ Wk,
                                              const float* __restrict__ Wv,
                                              const float* __restrict__ Wo) {
    int i = blockIdx.x * blockDim.x + threadIdx.x;
    int z = blockIdx.z;
    const float* src = (z == 0) ? Wq : (z == 1) ? Wk : (z == 2) ? Wv : Wo;
    unsigned short* dst = (z == 0) ? g_wq : (z == 1) ? g_wk : (z == 2) ? g_wv : g_wo;
    float4 v = ((const float4*)src)[i];
    ((uint2*)dst)[i] = make_uint2(pack_f16(v.x, v.y), pack_f16(v.z, v.w));
}

// ---------------------------------------------------------------------------
// GEMM: C[128x128 tile] = A[M,K] * B[N,K]^T.
// PASSES=1: single fp16 pass (A hi only). PASSES=2: A hi/lo 2-pass.
// 256 threads, 8 warps, warp tile 32x64. K-chunks of 64, double buffered.
// OUT_MODE: 0 = fp32 C, 2 = single fp16.
// ---------------------------------------------------------------------------
#define GROWB 144
#define TILE_B (128 * GROWB)           // 18432

template<int PASSES>
__device__ __forceinline__ void gemm_issue(
    uint32_t sbase, int buf, int tid,
    const unsigned short* __restrict__ Ahi, const unsigned short* __restrict__ Alo,
    const unsigned short* __restrict__ B,
    int rowBase, int colBase, int ch)
{
    const size_t kOff = (size_t)ch * 64;
    const uint32_t stage = sbase + buf * ((PASSES + 1) * TILE_B);
    const unsigned short* srcs[3];
    srcs[0] = Ahi + (size_t)rowBase * Dmodel + kOff;
    if (PASSES == 2) srcs[1] = Alo + (size_t)rowBase * Dmodel + kOff;
    srcs[PASSES] = B + (size_t)colBase * Dmodel + kOff;
#pragma unroll
    for (int t = 0; t <= PASSES; t++) {
        const unsigned short* src = srcs[t];
        const uint32_t dstT = stage + t * TILE_B;
#pragma unroll
        for (int it = 0; it < 4; it++) {
            int idx = it * 256 + tid;
            int r = idx >> 3;
            int j = idx & 7;
            CP_ASYNC16(dstT + r * GROWB + j * 16, src + (size_t)r * Dmodel + j * 8);
        }
    }
    CP_COMMIT();
}

template<int PASSES, int OUT_MODE>
__device__ __forceinline__ void gemm_core(
    const unsigned short* __restrict__ Ahi, const unsigned short* __restrict__ Alo,
    const unsigned short* __restrict__ B,
    float* __restrict__ C, unsigned short* __restrict__ Cf)
{
    extern __shared__ char smem[];
    const uint32_t sbase = smem_to_u32(smem);
    const int tid = threadIdx.x;
    const int wid = tid >> 5;
    const int lane = tid & 31;

    const int rowBase = blockIdx.y * 128;
    const int colBase = blockIdx.x * 128;
    const int m0 = (wid & 3) * 32;
    const int n0 = (wid >> 2) * 64;

    const int lr = (lane & 7) + (lane & 8);
    const int lk = (lane >> 4) << 3;

    float acc[2][8][4];
#pragma unroll
    for (int mt = 0; mt < 2; mt++)
#pragma unroll
        for (int nt = 0; nt < 8; nt++)
#pragma unroll
            for (int q = 0; q < 4; q++) acc[mt][nt][q] = 0.f;

    const int nch = Dmodel / 64;   // 32
    gemm_issue<PASSES>(sbase, 0, tid, Ahi, Alo, B, rowBase, colBase, 0);
    gemm_issue<PASSES>(sbase, 1, tid, Ahi, Alo, B, rowBase, colBase, 1);

    for (int ch = 0; ch < nch; ch++) {
        if (ch == nch - 1) { CP_WAIT0(); } else { CP_WAIT1(); }
        __syncthreads();

        const int buf = ch & 1;
        const uint32_t aHiB = sbase + buf * ((PASSES + 1) * TILE_B);
        const uint32_t aLoB = aHiB + TILE_B;
        const uint32_t bB = aHiB + PASSES * TILE_B;

#pragma unroll
        for (int ks = 0; ks < 4; ks++) {
            const int k0 = ks * 16;
            uint32_t ahi[2][4], alo[2][4];
#pragma unroll
            for (int mt = 0; mt < 2; mt++) {
                uint32_t off = (m0 + mt * 16 + lr) * GROWB + (k0 + lk) * 2;
                LDSM_X4(ahi[mt][0], ahi[mt][1], ahi[mt][2], ahi[mt][3], aHiB + off);
                if (PASSES == 2)
                    LDSM_X4(alo[mt][0], alo[mt][1], alo[mt][2], alo[mt][3], aLoB + off);
            }
            uint32_t bf[8][2];
#pragma unroll
            for (int jp = 0; jp < 4; jp++) {
                uint32_t off = (n0 + jp * 16 + lr) * GROWB + (k0 + lk) * 2;
                uint32_t r0, r1, r2, r3;
                LDSM_X4(r0, r1, r2, r3, bB + off);
                bf[2 * jp][0] = r0; bf[2 * jp][1] = r2;
                bf[2 * jp + 1][0] = r1; bf[2 * jp + 1][1] = r3;
            }
#pragma unroll
            for (int mt = 0; mt < 2; mt++)
#pragma unroll
                for (int nt = 0; nt < 8; nt++) MMA_F16(acc[mt][nt], ahi[mt], bf[nt]);
            if (PASSES == 2) {
#pragma unroll
                for (int mt = 0; mt < 2; mt++)
#pragma unroll
                    for (int nt = 0; nt < 8; nt++) MMA_F16(acc[mt][nt], alo[mt], bf[nt]);
            }
        }
        __syncthreads();
        if (ch + 2 < nch)
            gemm_issue<PASSES>(sbase, buf, tid, Ahi, Alo, B, rowBase, colBase, ch + 2);
    }

    const int cr = lane >> 2;
    const int cc = (lane & 3) * 2;
#pragma unroll
    for (int mt = 0; mt < 2; mt++) {
#pragma unroll
        for (int nt = 0; nt < 8; nt++) {
            const int row = rowBase + m0 + mt * 16 + cr;
            const int col = colBase + n0 + nt * 8 + cc;
            if (OUT_MODE == 2) {
                *(uint32_t*)(Cf + (size_t)row * Dmodel + col) = pack_f16(acc[mt][nt][0], acc[mt][nt][1]);
                *(uint32_t*)(Cf + (size_t)(row + 8) * Dmodel + col) = pack_f16(acc[mt][nt][2], acc[mt][nt][3]);
            } else {
                *(float2*)&C[(size_t)row * Dmodel + col] = make_float2(acc[mt][nt][0], acc[mt][nt][1]);
                *(float2*)&C[(size_t)(row + 8) * Dmodel + col] = make_float2(acc[mt][nt][2], acc[mt][nt][3]);
            }
        }
    }
}

#define GQKV_SMEM (2 * 2 * TILE_B)     // 73728
#define GWO_SMEM (2 * 3 * TILE_B)      // 110592

__global__ __launch_bounds__(256, 2) void gemm_qkv() {
    const int z = blockIdx.z;
    const unsigned short* B = (z == 0) ? g_wq : (z == 1) ? g_wk : g_wv;
    unsigned short* cf = (z == 0) ? g_qhi : (z == 1) ? g_khi : g_vhi;
    gemm_core<1, 2>(g_xhi, nullptr, B, nullptr, cf);
}

__global__ __launch_bounds__(256, 2) void gemm_wo(float* __restrict__ out) {
    gemm_core<2, 0>(g_yhi, g_ylo, g_wo, out, nullptr);
}

// ---------------------------------------------------------------------------
// Flash attention: 64-query CTAs, 128 threads (4 warps) -> 2 CTAs/SM.
// Q single fp16 (S single pass); P hi/lo kept for the PV product.
// ---------------------------------------------------------------------------
#define ASTRIDE 272
#define ATILE_B (64 * ASTRIDE)         // 17408
#define ASTAGE_B (2 * ATILE_B)         // 34816: Khi, Vhi
#define ATTN_SMEM (2 * ASTAGE_B)       // 69632

__device__ __forceinline__ void attn_issue_kv(uint32_t sbase, int buf, int tid,
                                              size_t hbase, int kt)
{
    const unsigned short* srcs[2] = {g_khi, g_vhi};
    const uint32_t stage = sbase + buf * ASTAGE_B;
#pragma unroll
    for (int t = 0; t < 2; t++) {
        const unsigned short* src = srcs[t] + hbase + (size_t)(kt * 64) * Dmodel;
        const uint32_t dstT = stage + t * ATILE_B;
#pragma unroll
        for (int it = 0; it < 8; it++) {
            int idx = it * 128 + tid;     // 0..1023
            int r = idx >> 4;             // row 0..63
            int j = idx & 15;             // 16B chunk
            CP_ASYNC16(dstT + r * ASTRIDE + j * 16, src + (size_t)r * Dmodel + j * 8);
        }
    }
    CP_COMMIT();
}

__global__ __launch_bounds__(128, 2) void attn_mma()
{
    extern __shared__ char smem[];
    const uint32_t sbase = smem_to_u32(smem);
    const int tid = threadIdx.x;
    const int wid = tid >> 5;        // 0..3
    const int lane = tid & 31;

    const int qt = (gridDim.x - 1) - blockIdx.x;   // heavy tiles first
    const int h = blockIdx.y;
    const int b = blockIdx.z;
    const size_t hbase = ((size_t)b * Sseq) * Dmodel + (size_t)h * HDdim;

    const int lr = (lane & 7) + (lane & 8);
    const int lk = (lane >> 4) << 3;
    const float kExp = 1.4426950408889634f * 0.08838834764831845f;

    // stage Q (64 x 128 fp16) through stage0 smem into register frags
    {
#pragma unroll
        for (int it = 0; it < 8; it++) {
            int idx = it * 128 + tid;    // 0..1023
            int r = idx >> 4;
            int j = idx & 15;
            const size_t goff = hbase + (size_t)(qt * 64 + r) * Dmodel + j * 8;
            CP_ASYNC16(sbase + r * ASTRIDE + j * 16, g_qhi + goff);
        }
        CP_COMMIT(); CP_WAIT0();
        __syncthreads();
    }
    uint32_t qf[8][4];
#pragma unroll
    for (int ks = 0; ks < 8; ks++) {
        uint32_t off = (wid * 16 + lr) * ASTRIDE + (ks * 16 + lk) * 2;
        LDSM_X4(qf[ks][0], qf[ks][1], qf[ks][2], qf[ks][3], sbase + off);
    }
    __syncthreads();

    float oacc[16][4];
#pragma unroll
    for (int nt = 0; nt < 16; nt++)
#pragma unroll
        for (int q = 0; q < 4; q++) oacc[nt][q] = 0.f;
    float m0 = -1e30f, m1 = -1e30f, l0 = 0.f, l1 = 0.f;

    const int nkt = qt + 1;
    attn_issue_kv(sbase, 0, tid, hbase, 0);
    if (nkt > 1) attn_issue_kv(sbase, 1, tid, hbase, 1);

    const int row0 = qt * 64 + wid * 16 + (lane >> 2);

    for (int kt = 0; kt < nkt; kt++) {
        if (kt == nkt - 1) { CP_WAIT0(); } else { CP_WAIT1(); }
        __syncthreads();

        const uint32_t stage = sbase + (kt & 1) * ASTAGE_B;
        const uint32_t kB = stage;
        const uint32_t vB = stage + ATILE_B;

        // S = Q K^T, single fp16 pass
        float sacc[8][4];
#pragma unroll
        for (int nt = 0; nt < 8; nt++)
#pragma unroll
            for (int q = 0; q < 4; q++) sacc[nt][q] = 0.f;
#pragma unroll
        for (int ks = 0; ks < 8; ks++) {
            uint32_t bh[8][2];
#pragma unroll
            for (int jp = 0; jp < 4; jp++) {
                uint32_t off = (jp * 16 + lr) * ASTRIDE + (ks * 16 + lk) * 2;
                uint32_t r0, r1, r2, r3;
                LDSM_X4(r0, r1, r2, r3, kB + off);
                bh[2 * jp][0] = r0; bh[2 * jp][1] = r2;
                bh[2 * jp + 1][0] = r1; bh[2 * jp + 1][1] = r3;
            }
#pragma unroll
            for (int nt = 0; nt < 8; nt++) MMA_F16(sacc[nt], qf[ks], bh[nt]);
        }

        // online softmax (base-2, scale folded), causal mask
        const bool needm = (kt * 64 + 63) > (qt * 64 + wid * 16);
        const int col0 = kt * 64 + 2 * (lane & 3);
        float mx0 = -1e30f, mx1 = -1e30f;
#pragma unroll
        for (int nt = 0; nt < 8; nt++) {
#pragma unroll
            for (int e = 0; e < 2; e++) {
                float v = sacc[nt][e] * kExp;
                if (needm && (col0 + nt * 8 + e > row0)) v = -1e30f;
                sacc[nt][e] = v;
                mx0 = fmaxf(mx0, v);
                float w = sacc[nt][2 + e] * kExp;
                if (needm && (col0 + nt * 8 + e > row0 + 8)) w = -1e30f;
                sacc[nt][2 + e] = w;
                mx1 = fmaxf(mx1, w);
            }
        }
        mx0 = fmaxf(mx0, __shfl_xor_sync(0xffffffffu, mx0, 1));
        mx0 = fmaxf(mx0, __shfl_xor_sync(0xffffffffu, mx0, 2));
        mx1 = fmaxf(mx1, __shfl_xor_sync(0xffffffffu, mx1, 1));
        mx1 = fmaxf(mx1, __shfl_xor_sync(0xffffffffu, mx1, 2));
        float mn0 = fmaxf(m0, mx0), mn1 = fmaxf(m1, mx1);
        float a0 = fast_ex2(m0 - mn0), a1 = fast_ex2(m1 - mn1);
#pragma unroll
        for (int nt = 0; nt < 16; nt++) {
            oacc[nt][0] *= a0; oacc[nt][1] *= a0;
            oacc[nt][2] *= a1; oacc[nt][3] *= a1;
        }
        float ls0 = 0.f, ls1 = 0.f;
#pragma unroll
        for (int nt = 0; nt < 8; nt++) {
#pragma unroll
            for (int e = 0; e < 2; e++) {
                float p0 = fast_ex2(sacc[nt][e] - mn0);
                float p1 = fast_ex2(sacc[nt][2 + e] - mn1);
                sacc[nt][e] = p0; sacc[nt][2 + e] = p1;
                ls0 += p0; ls1 += p1;
            }
        }
        ls0 += __shfl_xor_sync(0xffffffffu, ls0, 1);
        ls0 += __shfl_xor_sync(0xffffffffu, ls0, 2);
        ls1 += __shfl_xor_sync(0xffffffffu, ls1, 1);
        ls1 += __shfl_xor_sync(0xffffffffu, ls1, 2);
        l0 = l0 * a0 + ls0; l1 = l1 * a1 + ls1;
        m0 = mn0; m1 = mn1;

        // O += P V, 2-pass (P hi/lo, V fp16)
#pragma unroll
        for (int kstep = 0; kstep < 4; kstep++) {
            uint32_t ph[4], pl[4];
            pack_hilo(sacc[2 * kstep][0], sacc[2 * kstep][1], ph[0], pl[0]);
            pack_hilo(sacc[2 * kstep][2], sacc[2 * kstep][3], ph[1], pl[1]);
            pack_hilo(sacc[2 * kstep + 1][0], sacc[2 * kstep + 1][1], ph[2], pl[2]);
            pack_hilo(sacc[2 * kstep + 1][2], sacc[2 * kstep + 1][3], ph[3], pl[3]);
#pragma unroll
            for (int db = 0; db < 2; db++) {
                uint32_t bv[8][2];
#pragma unroll
                for (int dpi = 0; dpi < 4; dpi++) {
                    const int dp = db * 4 + dpi;
                    uint32_t off = (kstep * 16 + lr) * ASTRIDE + (dp * 16 + lk) * 2;
                    uint32_t v0, v1, v2, v3;
                    LDSM_X4_T(v0, v1, v2, v3, vB + off);
                    bv[2 * dpi][0] = v0; bv[2 * dpi][1] = v1;
                    bv[2 * dpi + 1][0] = v2; bv[2 * dpi + 1][1] = v3;
                }
#pragma unroll
                for (int dpi = 0; dpi < 4; dpi++) {
                    MMA_F16(oacc[2 * (db * 4 + dpi)], ph, bv[2 * dpi]);
                    MMA_F16(oacc[2 * (db * 4 + dpi) + 1], ph, bv[2 * dpi + 1]);
                }
#pragma unroll
                for (int dpi = 0; dpi < 4; dpi++) {
                    MMA_F16(oacc[2 * (db * 4 + dpi)], pl, bv[2 * dpi]);
                    MMA_F16(oacc[2 * (db * 4 + dpi) + 1], pl, bv[2 * dpi + 1]);
                }
            }
        }

        __syncthreads();
        if (kt + 2 < nkt)
            attn_issue_kv(sbase, kt & 1, tid, hbase, kt + 2);
    }

    const float inv0 = 1.f / l0;
    const float inv1 = 1.f / l1;
#pragma unroll
    for (int nt = 0; nt < 16; nt++) {
        const int col = nt * 8 + 2 * (lane & 3);
        const size_t i0 = ((size_t)b * Sseq + row0) * Dmodel + h * HDdim + col;
        const size_t i1 = ((size_t)b * Sseq + row0 + 8) * Dmodel + h * HDdim + col;
        uint32_t hh, ll;
        pack_hilo(oacc[nt][0] * inv0, oacc[nt][1] * inv0, hh, ll);
        *(uint32_t*)(g_yhi + i0) = hh;
        *(uint32_t*)(g_ylo + i0) = ll;
        pack_hilo(oacc[nt][2] * inv1, oacc[nt][3] * inv1, hh, ll);
        *(uint32_t*)(g_yhi + i1) = hh;
        *(uint32_t*)(g_ylo + i1) = ll;
    }
}

// ---------------------------------------------------------------------------
// launch
// ---------------------------------------------------------------------------
extern "C" void kernel_launch(void* const* d_in, const int* in_sizes, int n_in,
                              void* d_out, int out_size)
{
    (void)in_sizes; (void)n_in; (void)out_size;
    const float* x  = (const float*)d_in[0];
    const float* Wq = (const float*)d_in[2];
    const float* Wk = (const float*)d_in[3];
    const float* Wv = (const float*)d_in[4];
    const float* Wo = (const float*)d_in[5];
    float* out = (float*)d_out;

    cudaFuncSetAttribute(gemm_qkv, cudaFuncAttributeMaxDynamicSharedMemorySize, GQKV_SMEM);
    cudaFuncSetAttribute(gemm_wo, cudaFuncAttributeMaxDynamicSharedMemorySize, GWO_SMEM);
    cudaFuncSetAttribute(attn_mma, cudaFuncAttributeMaxDynamicSharedMemorySize, ATTN_SMEM);

    const int nX4 = Mrows * Dmodel / 4;
    const int nW4 = Dmodel * Dmodel / 4;

    conv_x<<<nX4 / 256, 256>>>(x);
    conv_w<<<dim3(nW4 / 256, 1, 4), 256>>>(Wq, Wk, Wv, Wo);

    gemm_qkv<<<dim3(Dmodel / 128, Mrows / 128, 3), 256, GQKV_SMEM>>>();
    attn_mma<<<dim3(Sseq / 64, Hheads, Bsz), 128, ATTN_SMEM>>>();
    gemm_wo<<<dim3(Dmodel / 128, Mrows / 128, 1), 256, GWO_SMEM>>>(out);
}

// round 10
// speedup vs baseline: 7.4245x; 1.2268x over previous
#include <cuda_runtime.h>
#include <cuda_fp16.h>
#include <math.h>
#include <stdint.h>

#define Bsz 2
#define Sseq 2048
#define Dmodel 2048
#define Hheads 16
#define HDdim 128
#define Mrows (Bsz * Sseq)   // 4096

// ---------------- scratch (fp16 payloads in ushort arrays) ----------------
__device__ unsigned short g_xhi[Mrows * Dmodel];
__device__ unsigned short g_qhi[Mrows * Dmodel];
__device__ unsigned short g_khi[Mrows * Dmodel];
__device__ unsigned short g_vhi[Mrows * Dmodel];
__device__ unsigned short g_yhi[Mrows * Dmodel];
__device__ unsigned short g_wq[Dmodel * Dmodel];
__device__ unsigned short g_wk[Dmodel * Dmodel];
__device__ unsigned short g_wv[Dmodel * Dmodel];
__device__ unsigned short g_wo[Dmodel * Dmodel];

// ---------------- helpers ----------------
__device__ __forceinline__ uint32_t smem_to_u32(const void* p) {
    uint32_t a;
    asm("{ .reg .u64 t; cvta.to.shared.u64 t, %1; cvt.u32.u64 %0, t; }" : "=r"(a) : "l"(p));
    return a;
}

#define CP_ASYNC16(dst_u32, src_ptr) \
    asm volatile("cp.async.cg.shared.global [%0], [%1], 16;" :: "r"(dst_u32), "l"(src_ptr))
#define CP_COMMIT() asm volatile("cp.async.commit_group;")
#define CP_WAIT1()  asm volatile("cp.async.wait_group 1;")
#define CP_WAIT0()  asm volatile("cp.async.wait_group 0;")

#define LDSM_X4(r0, r1, r2, r3, addr) \
    asm volatile("ldmatrix.sync.aligned.m8n8.x4.shared.b16 {%0,%1,%2,%3}, [%4];" \
                 : "=r"(r0), "=r"(r1), "=r"(r2), "=r"(r3) : "r"(addr))
#define LDSM_X4_T(r0, r1, r2, r3, addr) \
    asm volatile("ldmatrix.sync.aligned.m8n8.x4.trans.shared.b16 {%0,%1,%2,%3}, [%4];" \
                 : "=r"(r0), "=r"(r1), "=r"(r2), "=r"(r3) : "r"(addr))

#define MMA_F16(c, a, b) \
    asm volatile("mma.sync.aligned.m16n8k16.row.col.f32.f16.f16.f32 " \
                 "{%0,%1,%2,%3},{%4,%5,%6,%7},{%8,%9},{%0,%1,%2,%3};" \
                 : "+f"((c)[0]), "+f"((c)[1]), "+f"((c)[2]), "+f"((c)[3]) \
                 : "r"((a)[0]), "r"((a)[1]), "r"((a)[2]), "r"((a)[3]), \
                   "r"((b)[0]), "r"((b)[1]))

__device__ __forceinline__ float fast_ex2(float x) {
    float y; asm("ex2.approx.f32 %0, %1;" : "=f"(y) : "f"(x)); return y;
}

__device__ __forceinline__ uint32_t pack_f16(float a, float b) {
    __half2 hv = __floats2half2_rn(a, b);
    return *reinterpret_cast<uint32_t*>(&hv);
}

// ---------------------------------------------------------------------------
// converts: fp32 -> fp16
// ---------------------------------------------------------------------------
__global__ __launch_bounds__(256) void conv_x(const float* __restrict__ x) {
    int i = blockIdx.x * blockDim.x + threadIdx.x;
    float4 v = ((const float4*)x)[i];
    ((uint2*)g_xhi)[i] = make_uint2(pack_f16(v.x, v.y), pack_f16(v.z, v.w));
}

__global__ __launch_bounds__(256) void conv_w(const float* __restrict__ Wq,
                                              const float* __restrict__ Wk,
                                              const float* __restrict__ Wv,
                                              const float* __restrict__ Wo) {
    int i = blockIdx.x * blockDim.x + threadIdx.x;
    int z = blockIdx.z;
    const float* src = (z == 0) ? Wq : (z == 1) ? Wk : (z == 2) ? Wv : Wo;
    unsigned short* dst = (z == 0) ? g_wq : (z == 1) ? g_wk : (z == 2) ? g_wv : g_wo;
    float4 v = ((const float4*)src)[i];
    ((uint2*)dst)[i] = make_uint2(pack_f16(v.x, v.y), pack_f16(v.z, v.w));
}

// ---------------------------------------------------------------------------
// GEMM: C[128x128 tile] = A[M,K] * B[N,K]^T, single fp16 pass.
// 256 threads, 8 warps, warp tile 32x64. K-chunks of 64, double buffer.
// OUT_MODE: 0 = fp32 C, 2 = fp16 (scaled by 'oscale').
// ---------------------------------------------------------------------------
#define GROWB 144
#define TILE_B (128 * GROWB)           // 18432
#define G_SMEM (2 * 2 * TILE_B)        // 73728

__device__ __forceinline__ void gemm_issue(
    uint32_t sbase, int buf, int tid,
    const unsigned short* __restrict__ A, const unsigned short* __restrict__ B,
    int rowBase, int colBase, int ch)
{
    const size_t kOff = (size_t)ch * 64;
    const uint32_t stage = sbase + buf * (2 * TILE_B);
    const unsigned short* srcs[2] = {
        A + (size_t)rowBase * Dmodel + kOff,
        B + (size_t)colBase * Dmodel + kOff };
#pragma unroll
    for (int t = 0; t < 2; t++) {
        const unsigned short* src = srcs[t];
        const uint32_t dstT = stage + t * TILE_B;
#pragma unroll
        for (int it = 0; it < 4; it++) {
            int idx = it * 256 + tid;
            int r = idx >> 3;
            int j = idx & 7;
            CP_ASYNC16(dstT + r * GROWB + j * 16, src + (size_t)r * Dmodel + j * 8);
        }
    }
    CP_COMMIT();
}

template<int OUT_MODE>
__device__ __forceinline__ void gemm_core(
    const unsigned short* __restrict__ A, const unsigned short* __restrict__ B,
    float* __restrict__ C, unsigned short* __restrict__ Cf, float oscale)
{
    extern __shared__ char smem[];
    const uint32_t sbase = smem_to_u32(smem);
    const int tid = threadIdx.x;
    const int wid = tid >> 5;
    const int lane = tid & 31;

    const int rowBase = blockIdx.y * 128;
    const int colBase = blockIdx.x * 128;
    const int m0 = (wid & 3) * 32;
    const int n0 = (wid >> 2) * 64;

    const int lr = (lane & 7) + (lane & 8);
    const int lk = (lane >> 4) << 3;

    float acc[2][8][4];
#pragma unroll
    for (int mt = 0; mt < 2; mt++)
#pragma unroll
        for (int nt = 0; nt < 8; nt++)
#pragma unroll
            for (int q = 0; q < 4; q++) acc[mt][nt][q] = 0.f;

    const int nch = Dmodel / 64;   // 32
    gemm_issue(sbase, 0, tid, A, B, rowBase, colBase, 0);
    gemm_issue(sbase, 1, tid, A, B, rowBase, colBase, 1);

    for (int ch = 0; ch < nch; ch++) {
        if (ch == nch - 1) { CP_WAIT0(); } else { CP_WAIT1(); }
        __syncthreads();

        const int buf = ch & 1;
        const uint32_t aB = sbase + buf * (2 * TILE_B);
        const uint32_t bB = aB + TILE_B;

#pragma unroll
        for (int ks = 0; ks < 4; ks++) {
            const int k0 = ks * 16;
            uint32_t af[2][4];
#pragma unroll
            for (int mt = 0; mt < 2; mt++) {
                uint32_t off = (m0 + mt * 16 + lr) * GROWB + (k0 + lk) * 2;
                LDSM_X4(af[mt][0], af[mt][1], af[mt][2], af[mt][3], aB + off);
            }
            uint32_t bf[8][2];
#pragma unroll
            for (int jp = 0; jp < 4; jp++) {
                uint32_t off = (n0 + jp * 16 + lr) * GROWB + (k0 + lk) * 2;
                uint32_t r0, r1, r2, r3;
                LDSM_X4(r0, r1, r2, r3, bB + off);
                bf[2 * jp][0] = r0; bf[2 * jp][1] = r2;
                bf[2 * jp + 1][0] = r1; bf[2 * jp + 1][1] = r3;
            }
#pragma unroll
            for (int mt = 0; mt < 2; mt++)
#pragma unroll
                for (int nt = 0; nt < 8; nt++) MMA_F16(acc[mt][nt], af[mt], bf[nt]);
        }
        __syncthreads();
        if (ch + 2 < nch)
            gemm_issue(sbase, buf, tid, A, B, rowBase, colBase, ch + 2);
    }

    const int cr = lane >> 2;
    const int cc = (lane & 3) * 2;
#pragma unroll
    for (int mt = 0; mt < 2; mt++) {
#pragma unroll
        for (int nt = 0; nt < 8; nt++) {
            const int row = rowBase + m0 + mt * 16 + cr;
            const int col = colBase + n0 + nt * 8 + cc;
            if (OUT_MODE == 2) {
                *(uint32_t*)(Cf + (size_t)row * Dmodel + col) =
                    pack_f16(acc[mt][nt][0] * oscale, acc[mt][nt][1] * oscale);
                *(uint32_t*)(Cf + (size_t)(row + 8) * Dmodel + col) =
                    pack_f16(acc[mt][nt][2] * oscale, acc[mt][nt][3] * oscale);
            } else {
                *(float2*)&C[(size_t)row * Dmodel + col] = make_float2(acc[mt][nt][0], acc[mt][nt][1]);
                *(float2*)&C[(size_t)(row + 8) * Dmodel + col] = make_float2(acc[mt][nt][2], acc[mt][nt][3]);
            }
        }
    }
}

__global__ __launch_bounds__(256, 2) void gemm_qkv() {
    const int z = blockIdx.z;
    const unsigned short* B = (z == 0) ? g_wq : (z == 1) ? g_wk : g_wv;
    unsigned short* cf = (z == 0) ? g_qhi : (z == 1) ? g_khi : g_vhi;
    // fold softmax scale (log2e / sqrt(128)) into Q
    const float osc = (z == 0) ? (1.4426950408889634f * 0.08838834764831845f) : 1.0f;
    gemm_core<2>(g_xhi, B, nullptr, cf, osc);
}

__global__ __launch_bounds__(256, 2) void gemm_wo(float* __restrict__ out) {
    gemm_core<0>(g_yhi, g_wo, out, nullptr, 1.0f);
}

// ---------------------------------------------------------------------------
// Flash attention: 64-query CTAs, 128 threads (4 warps), 2 CTAs/SM.
// Q pre-scaled fp16 (S single pass); P single fp16 (PV single pass).
// ---------------------------------------------------------------------------
#define ASTRIDE 272
#define ATILE_B (64 * ASTRIDE)         // 17408
#define ASTAGE_B (2 * ATILE_B)         // 34816: K, V
#define ATTN_SMEM (2 * ASTAGE_B)       // 69632

__device__ __forceinline__ void attn_issue_kv(uint32_t sbase, int buf, int tid,
                                              size_t hbase, int kt)
{
    const unsigned short* srcs[2] = {g_khi, g_vhi};
    const uint32_t stage = sbase + buf * ASTAGE_B;
#pragma unroll
    for (int t = 0; t < 2; t++) {
        const unsigned short* src = srcs[t] + hbase + (size_t)(kt * 64) * Dmodel;
        const uint32_t dstT = stage + t * ATILE_B;
#pragma unroll
        for (int it = 0; it < 8; it++) {
            int idx = it * 128 + tid;
            int r = idx >> 4;
            int j = idx & 15;
            CP_ASYNC16(dstT + r * ASTRIDE + j * 16, src + (size_t)r * Dmodel + j * 8);
        }
    }
    CP_COMMIT();
}

__global__ __launch_bounds__(128, 2) void attn_mma()
{
    extern __shared__ char smem[];
    const uint32_t sbase = smem_to_u32(smem);
    const int tid = threadIdx.x;
    const int wid = tid >> 5;
    const int lane = tid & 31;

    const int qt = (gridDim.x - 1) - blockIdx.x;   // heavy tiles first
    const int h = blockIdx.y;
    const int b = blockIdx.z;
    const size_t hbase = ((size_t)b * Sseq) * Dmodel + (size_t)h * HDdim;

    const int lr = (lane & 7) + (lane & 8);
    const int lk = (lane >> 4) << 3;

    // stage Q (64 x 128 fp16, pre-scaled) through stage0 smem into frags
    {
#pragma unroll
        for (int it = 0; it < 8; it++) {
            int idx = it * 128 + tid;
            int r = idx >> 4;
            int j = idx & 15;
            const size_t goff = hbase + (size_t)(qt * 64 + r) * Dmodel + j * 8;
            CP_ASYNC16(sbase + r * ASTRIDE + j * 16, g_qhi + goff);
        }
        CP_COMMIT(); CP_WAIT0();
        __syncthreads();
    }
    uint32_t qf[8][4];
#pragma unroll
    for (int ks = 0; ks < 8; ks++) {
        uint32_t off = (wid * 16 + lr) * ASTRIDE + (ks * 16 + lk) * 2;
        LDSM_X4(qf[ks][0], qf[ks][1], qf[ks][2], qf[ks][3], sbase + off);
    }
    __syncthreads();

    float oacc[16][4];
#pragma unroll
    for (int nt = 0; nt < 16; nt++)
#pragma unroll
        for (int q = 0; q < 4; q++) oacc[nt][q] = 0.f;
    float m0 = -1e30f, m1 = -1e30f, l0 = 0.f, l1 = 0.f;

    const int nkt = qt + 1;
    attn_issue_kv(sbase, 0, tid, hbase, 0);
    if (nkt > 1) attn_issue_kv(sbase, 1, tid, hbase, 1);

    const int row0 = qt * 64 + wid * 16 + (lane >> 2);

    for (int kt = 0; kt < nkt; kt++) {
        if (kt == nkt - 1) { CP_WAIT0(); } else { CP_WAIT1(); }
        __syncthreads();

        const uint32_t stage = sbase + (kt & 1) * ASTAGE_B;
        const uint32_t kB = stage;
        const uint32_t vB = stage + ATILE_B;

        // S = Q K^T (Q pre-scaled; S already in log2 units)
        float sacc[8][4];
#pragma unroll
        for (int nt = 0; nt < 8; nt++)
#pragma unroll
            for (int q = 0; q < 4; q++) sacc[nt][q] = 0.f;
#pragma unroll
        for (int ks = 0; ks < 8; ks++) {
            uint32_t bh[8][2];
#pragma unroll
            for (int jp = 0; jp < 4; jp++) {
                uint32_t off = (jp * 16 + lr) * ASTRIDE + (ks * 16 + lk) * 2;
                uint32_t r0, r1, r2, r3;
                LDSM_X4(r0, r1, r2, r3, kB + off);
                bh[2 * jp][0] = r0; bh[2 * jp][1] = r2;
                bh[2 * jp + 1][0] = r1; bh[2 * jp + 1][1] = r3;
            }
#pragma unroll
            for (int nt = 0; nt < 8; nt++) MMA_F16(sacc[nt], qf[ks], bh[nt]);
        }

        // causal mask: only the diagonal k-tile (kt == qt) needs it
        if (kt == qt) {
            const int col0 = kt * 64 + 2 * (lane & 3);
#pragma unroll
            for (int nt = 0; nt < 8; nt++) {
#pragma unroll
                for (int e = 0; e < 2; e++) {
                    if (col0 + nt * 8 + e > row0) sacc[nt][e] = -1e30f;
                    if (col0 + nt * 8 + e > row0 + 8) sacc[nt][2 + e] = -1e30f;
                }
            }
        }

        // online softmax in base-2
        float mx0 = -1e30f, mx1 = -1e30f;
#pragma unroll
        for (int nt = 0; nt < 8; nt++) {
            mx0 = fmaxf(mx0, fmaxf(sacc[nt][0], sacc[nt][1]));
            mx1 = fmaxf(mx1, fmaxf(sacc[nt][2], sacc[nt][3]));
        }
        mx0 = fmaxf(mx0, __shfl_xor_sync(0xffffffffu, mx0, 1));
        mx0 = fmaxf(mx0, __shfl_xor_sync(0xffffffffu, mx0, 2));
        mx1 = fmaxf(mx1, __shfl_xor_sync(0xffffffffu, mx1, 1));
        mx1 = fmaxf(mx1, __shfl_xor_sync(0xffffffffu, mx1, 2));
        float mn0 = fmaxf(m0, mx0), mn1 = fmaxf(m1, mx1);
        float a0 = fast_ex2(m0 - mn0), a1 = fast_ex2(m1 - mn1);
#pragma unroll
        for (int nt = 0; nt < 16; nt++) {
            oacc[nt][0] *= a0; oacc[nt][1] *= a0;
            oacc[nt][2] *= a1; oacc[nt][3] *= a1;
        }
        float ls0 = 0.f, ls1 = 0.f;
#pragma unroll
        for (int nt = 0; nt < 8; nt++) {
            float p0 = fast_ex2(sacc[nt][0] - mn0);
            float p1 = fast_ex2(sacc[nt][1] - mn0);
            float p2 = fast_ex2(sacc[nt][2] - mn1);
            float p3 = fast_ex2(sacc[nt][3] - mn1);
            sacc[nt][0] = p0; sacc[nt][1] = p1; sacc[nt][2] = p2; sacc[nt][3] = p3;
            ls0 += p0 + p1; ls1 += p2 + p3;
        }
        ls0 += __shfl_xor_sync(0xffffffffu, ls0, 1);
        ls0 += __shfl_xor_sync(0xffffffffu, ls0, 2);
        ls1 += __shfl_xor_sync(0xffffffffu, ls1, 1);
        ls1 += __shfl_xor_sync(0xffffffffu, ls1, 2);
        l0 = l0 * a0 + ls0; l1 = l1 * a1 + ls1;
        m0 = mn0; m1 = mn1;

        // O += P V, single fp16 pass
#pragma unroll
        for (int kstep = 0; kstep < 4; kstep++) {
            uint32_t ph[4];
            ph[0] = pack_f16(sacc[2 * kstep][0], sacc[2 * kstep][1]);
            ph[1] = pack_f16(sacc[2 * kstep][2], sacc[2 * kstep][3]);
            ph[2] = pack_f16(sacc[2 * kstep + 1][0], sacc[2 * kstep + 1][1]);
            ph[3] = pack_f16(sacc[2 * kstep + 1][2], sacc[2 * kstep + 1][3]);
#pragma unroll
            for (int db = 0; db < 2; db++) {
                uint32_t bv[8][2];
#pragma unroll
                for (int dpi = 0; dpi < 4; dpi++) {
                    const int dp = db * 4 + dpi;
                    uint32_t off = (kstep * 16 + lr) * ASTRIDE + (dp * 16 + lk) * 2;
                    uint32_t v0, v1, v2, v3;
                    LDSM_X4_T(v0, v1, v2, v3, vB + off);
                    bv[2 * dpi][0] = v0; bv[2 * dpi][1] = v1;
                    bv[2 * dpi + 1][0] = v2; bv[2 * dpi + 1][1] = v3;
                }
#pragma unroll
                for (int dpi = 0; dpi < 4; dpi++) {
                    MMA_F16(oacc[2 * (db * 4 + dpi)], ph, bv[2 * dpi]);
                    MMA_F16(oacc[2 * (db * 4 + dpi) + 1], ph, bv[2 * dpi + 1]);
                }
            }
        }

        __syncthreads();
        if (kt + 2 < nkt)
            attn_issue_kv(sbase, kt & 1, tid, hbase, kt + 2);
    }

    const float inv0 = 1.f / l0;
    const float inv1 = 1.f / l1;
#pragma unroll
    for (int nt = 0; nt < 16; nt++) {
        const int col = nt * 8 + 2 * (lane & 3);
        const size_t i0 = ((size_t)b * Sseq + row0) * Dmodel + h * HDdim + col;
        const size_t i1 = ((size_t)b * Sseq + row0 + 8) * Dmodel + h * HDdim + col;
        *(uint32_t*)(g_yhi + i0) = pack_f16(oacc[nt][0] * inv0, oacc[nt][1] * inv0);
        *(uint32_t*)(g_yhi + i1) = pack_f16(oacc[nt][2] * inv1, oacc[nt][3] * inv1);
    }
}

// ---------------------------------------------------------------------------
// launch
// ---------------------------------------------------------------------------
extern "C" void kernel_launch(void* const* d_in, const int* in_sizes, int n_in,
                              void* d_out, int out_size)
{
    (void)in_sizes; (void)n_in; (void)out_size;
    const float* x  = (const float*)d_in[0];
    const float* Wq = (const float*)d_in[2];
    const float* Wk = (const float*)d_in[3];
    const float* Wv = (const float*)d_in[4];
    const float* Wo = (const float*)d_in[5];
    float* out = (float*)d_out;

    cudaFuncSetAttribute(gemm_qkv, cudaFuncAttributeMaxDynamicSharedMemorySize, G_SMEM);
    cudaFuncSetAttribute(gemm_wo, cudaFuncAttributeMaxDynamicSharedMemorySize, G_SMEM);
    cudaFuncSetAttribute(attn_mma, cudaFuncAttributeMaxDynamicSharedMemorySize, ATTN_SMEM);

    const int nX4 = Mrows * Dmodel / 4;
    const int nW4 = Dmodel * Dmodel / 4;

    conv_x<<<nX4 / 256, 256>>>(x);
    conv_w<<<dim3(nW4 / 256, 1, 4), 256>>>(Wq, Wk, Wv, Wo);

    gemm_qkv<<<dim3(Dmodel / 128, Mrows / 128, 3), 256, G_SMEM>>>();
    attn_mma<<<dim3(Sseq / 64, Hheads, Bsz), 128, ATTN_SMEM>>>();
    gemm_wo<<<dim3(Dmodel / 128, Mrows / 128, 1), 256, G_SMEM>>>(out);
}